// round 1
// baseline (speedup 1.0000x reference)
#include <cuda_runtime.h>
#include <math.h>

#define B_    2
#define S_    2048
#define DIN   1024
#define DOUT  1024
#define NH    16
#define HD_   64
#define WIN   256
#define SCALE 0.125f

// Scratch (allocation-free rule: device globals)
__device__ float g_q[B_*NH*S_*HD_];    // [b,h,s,hd]
__device__ float g_k[B_*NH*S_*HD_];
__device__ float g_v[B_*NH*S_*HD_];
__device__ float g_ctx[B_*S_*DOUT];    // [b,s,h*hd]

// ---------------------------------------------------------------------------
// GEMM: C[m][n] = sum_k A[m][k] * Bmat[n][k]   (both K-contiguous, "NT")
// BM=128, BN=64, BK=16, 256 threads, per-thread tile 8x4.
// ---------------------------------------------------------------------------
#define PA 132   // smem pitch for A (transposed [k][m]), 4-aligned, bank-spread
#define PB 68    // smem pitch for B (transposed [k][n]), 4-aligned

__global__ __launch_bounds__(256) void qkv_gemm(const float* __restrict__ x,
                                                const float* __restrict__ w)
{
    __shared__ float As[16 * PA];
    __shared__ float Bs[16 * PB];

    const int m0 = blockIdx.y * 128;
    const int n0 = blockIdx.x * 64;
    const int t  = threadIdx.x;
    const int ty = t >> 4;       // 0..15 -> M
    const int tx = t & 15;       // 0..15 -> N

    float acc[8][4];
#pragma unroll
    for (int r = 0; r < 8; r++)
#pragma unroll
        for (int c = 0; c < 4; c++) acc[r][c] = 0.f;

    for (int k0 = 0; k0 < DIN; k0 += 16) {
        // A tile: 128 rows x 16 k = 512 float4
#pragma unroll
        for (int i = 0; i < 2; i++) {
            int v   = t + i * 256;
            int row = v >> 2;
            int c4  = v & 3;
            float4 a = *(const float4*)(x + (size_t)(m0 + row) * DIN + k0 + c4 * 4);
            As[(c4 * 4 + 0) * PA + row] = a.x;
            As[(c4 * 4 + 1) * PA + row] = a.y;
            As[(c4 * 4 + 2) * PA + row] = a.z;
            As[(c4 * 4 + 3) * PA + row] = a.w;
        }
        // B tile: 64 rows x 16 k = 256 float4
        {
            int row = t >> 2;
            int c4  = t & 3;
            float4 b = *(const float4*)(w + (size_t)(n0 + row) * DIN + k0 + c4 * 4);
            Bs[(c4 * 4 + 0) * PB + row] = b.x;
            Bs[(c4 * 4 + 1) * PB + row] = b.y;
            Bs[(c4 * 4 + 2) * PB + row] = b.z;
            Bs[(c4 * 4 + 3) * PB + row] = b.w;
        }
        __syncthreads();

#pragma unroll
        for (int kk = 0; kk < 16; kk++) {
            float4 a0 = *(float4*)&As[kk * PA + ty * 8];
            float4 a1 = *(float4*)&As[kk * PA + ty * 8 + 4];
            float4 b0 = *(float4*)&Bs[kk * PB + tx * 4];
            float av[8] = {a0.x, a0.y, a0.z, a0.w, a1.x, a1.y, a1.z, a1.w};
            float bv[4] = {b0.x, b0.y, b0.z, b0.w};
#pragma unroll
            for (int r = 0; r < 8; r++)
#pragma unroll
                for (int c = 0; c < 4; c++) acc[r][c] = fmaf(av[r], bv[c], acc[r][c]);
        }
        __syncthreads();
    }

    // Epilogue: scatter to g_q / g_k / g_v in [b,h,s,hd] layout.
    // n0 is a multiple of 64 -> entire block has one (which, h).
    const int bidx  = m0 >> 11;           // batch
    const int which = n0 >> 10;           // 0=q 1=k 2=v
    const int h     = (n0 >> 6) & (NH - 1);
    float* dst = (which == 0) ? g_q : (which == 1) ? g_k : g_v;
    const size_t headbase = (size_t)(bidx * NH + h) * S_ * HD_;

#pragma unroll
    for (int r = 0; r < 8; r++) {
        int m = m0 + ty * 8 + r;
        int s = m & (S_ - 1);
        float4 v4 = make_float4(acc[r][0], acc[r][1], acc[r][2], acc[r][3]);
        *(float4*)(dst + headbase + (size_t)s * HD_ + tx * 4) = v4;
    }
}

__global__ __launch_bounds__(256) void out_gemm(const float* __restrict__ w,
                                                const float* __restrict__ bias,
                                                float* __restrict__ out)
{
    __shared__ float As[16 * PA];
    __shared__ float Bs[16 * PB];

    const int m0 = blockIdx.y * 128;
    const int n0 = blockIdx.x * 64;
    const int t  = threadIdx.x;
    const int ty = t >> 4;
    const int tx = t & 15;

    float acc[8][4];
#pragma unroll
    for (int r = 0; r < 8; r++)
#pragma unroll
        for (int c = 0; c < 4; c++) acc[r][c] = 0.f;

    for (int k0 = 0; k0 < DOUT; k0 += 16) {
#pragma unroll
        for (int i = 0; i < 2; i++) {
            int v   = t + i * 256;
            int row = v >> 2;
            int c4  = v & 3;
            float4 a = *(const float4*)(g_ctx + (size_t)(m0 + row) * DOUT + k0 + c4 * 4);
            As[(c4 * 4 + 0) * PA + row] = a.x;
            As[(c4 * 4 + 1) * PA + row] = a.y;
            As[(c4 * 4 + 2) * PA + row] = a.z;
            As[(c4 * 4 + 3) * PA + row] = a.w;
        }
        {
            int row = t >> 2;
            int c4  = t & 3;
            float4 b = *(const float4*)(w + (size_t)(n0 + row) * DOUT + k0 + c4 * 4);
            Bs[(c4 * 4 + 0) * PB + row] = b.x;
            Bs[(c4 * 4 + 1) * PB + row] = b.y;
            Bs[(c4 * 4 + 2) * PB + row] = b.z;
            Bs[(c4 * 4 + 3) * PB + row] = b.w;
        }
        __syncthreads();

#pragma unroll
        for (int kk = 0; kk < 16; kk++) {
            float4 a0 = *(float4*)&As[kk * PA + ty * 8];
            float4 a1 = *(float4*)&As[kk * PA + ty * 8 + 4];
            float4 b0 = *(float4*)&Bs[kk * PB + tx * 4];
            float av[8] = {a0.x, a0.y, a0.z, a0.w, a1.x, a1.y, a1.z, a1.w};
            float bv[4] = {b0.x, b0.y, b0.z, b0.w};
#pragma unroll
            for (int r = 0; r < 8; r++)
#pragma unroll
                for (int c = 0; c < 4; c++) acc[r][c] = fmaf(av[r], bv[c], acc[r][c]);
        }
        __syncthreads();
    }

    float4 bb = *(const float4*)(bias + n0 + tx * 4);
#pragma unroll
    for (int r = 0; r < 8; r++) {
        int m = m0 + ty * 8 + r;
        float4 v4 = make_float4(acc[r][0] + bb.x, acc[r][1] + bb.y,
                                acc[r][2] + bb.z, acc[r][3] + bb.w);
        *(float4*)(out + (size_t)m * DOUT + n0 + tx * 4) = v4;
    }
}

// ---------------------------------------------------------------------------
// Sliding-window attention, flash-style. One block = 64 queries of one (b,h).
// Thread grid 16x16; thread (ty,tx) owns S/O rows 4ty..4ty+3, cols 4tx..4tx+3.
// ---------------------------------------------------------------------------
#define PQ 68   // pitch for transposed Q/K [d][i] and straight V [j][d]
#define PP 65   // pitch for P [i][j]

__device__ __forceinline__ float allreduce_max16(float v) {
#pragma unroll
    for (int off = 8; off; off >>= 1)
        v = fmaxf(v, __shfl_xor_sync(0xffffffffu, v, off, 16));
    return v;
}
__device__ __forceinline__ float allreduce_sum16(float v) {
#pragma unroll
    for (int off = 8; off; off >>= 1)
        v += __shfl_xor_sync(0xffffffffu, v, off, 16);
    return v;
}

__global__ __launch_bounds__(256) void attn_kernel()
{
    extern __shared__ float sm[];
    float* Qs = sm;                 // [64][PQ] transposed: Qs[d*PQ + i]
    float* Ks = Qs + 64 * PQ;       // [64][PQ] transposed: Ks[d*PQ + j]
    float* Vs = Ks + 64 * PQ;       // [64][PQ] straight:   Vs[j*PQ + d]
    float* Ps = Vs + 64 * PQ;       // [64][PP]:            Ps[i*PP + j]

    const int q0 = blockIdx.x * 64;
    const int h  = blockIdx.y;
    const int b  = blockIdx.z;
    const int t  = threadIdx.x;
    const int ty = t >> 4;
    const int tx = t & 15;

    const size_t hb = (size_t)(b * NH + h) * S_ * HD_;
    const float* qbase = g_q + hb;
    const float* kbase = g_k + hb;
    const float* vbase = g_v + hb;

    // Load Q tile transposed
#pragma unroll
    for (int i2 = 0; i2 < 4; i2++) {
        int v   = t + i2 * 256;
        int row = v >> 4;
        int c4  = v & 15;
        float4 a = *(const float4*)(qbase + (size_t)(q0 + row) * HD_ + c4 * 4);
        Qs[(c4 * 4 + 0) * PQ + row] = a.x;
        Qs[(c4 * 4 + 1) * PQ + row] = a.y;
        Qs[(c4 * 4 + 2) * PQ + row] = a.z;
        Qs[(c4 * 4 + 3) * PQ + row] = a.w;
    }

    float o[4][4];
    float m_i[4], l_i[4];
#pragma unroll
    for (int r = 0; r < 4; r++) {
        m_i[r] = -INFINITY;
        l_i[r] = 0.f;
#pragma unroll
        for (int c = 0; c < 4; c++) o[r][c] = 0.f;
    }

    int kc_start = q0 - WIN; if (kc_start < 0) kc_start = 0;
    int kc_end   = q0 + 64 + WIN; if (kc_end > S_) kc_end = S_;

    for (int kc = kc_start; kc < kc_end; kc += 64) {
        __syncthreads();   // prev chunk's P@V done before overwriting Ks/Vs
        // Load K (transposed) and V (straight)
#pragma unroll
        for (int i2 = 0; i2 < 4; i2++) {
            int v   = t + i2 * 256;
            int row = v >> 4;
            int c4  = v & 15;
            float4 a = *(const float4*)(kbase + (size_t)(kc + row) * HD_ + c4 * 4);
            Ks[(c4 * 4 + 0) * PQ + row] = a.x;
            Ks[(c4 * 4 + 1) * PQ + row] = a.y;
            Ks[(c4 * 4 + 2) * PQ + row] = a.z;
            Ks[(c4 * 4 + 3) * PQ + row] = a.w;
            float4 vv = *(const float4*)(vbase + (size_t)(kc + row) * HD_ + c4 * 4);
            *(float4*)&Vs[row * PQ + c4 * 4] = vv;
        }
        __syncthreads();

        // S = Q @ K^T  (contraction over d)
        float s[4][4];
#pragma unroll
        for (int r = 0; r < 4; r++)
#pragma unroll
            for (int c = 0; c < 4; c++) s[r][c] = 0.f;

#pragma unroll 8
        for (int d = 0; d < 64; d++) {
            float4 qf = *(float4*)&Qs[d * PQ + ty * 4];
            float4 kf = *(float4*)&Ks[d * PQ + tx * 4];
            float qv[4] = {qf.x, qf.y, qf.z, qf.w};
            float kv[4] = {kf.x, kf.y, kf.z, kf.w};
#pragma unroll
            for (int r = 0; r < 4; r++)
#pragma unroll
                for (int c = 0; c < 4; c++) s[r][c] = fmaf(qv[r], kv[c], s[r][c]);
        }

        // Mask + scale + online softmax
#pragma unroll
        for (int r = 0; r < 4; r++) {
            int qg = q0 + ty * 4 + r;
            float mc = -INFINITY;
#pragma unroll
            for (int c = 0; c < 4; c++) {
                int kg = kc + tx * 4 + c;
                int dd = qg - kg; if (dd < 0) dd = -dd;
                s[r][c] = (dd <= WIN) ? s[r][c] * SCALE : -INFINITY;
                mc = fmaxf(mc, s[r][c]);
            }
            mc = allreduce_max16(mc);

            float mn    = fmaxf(m_i[r], mc);
            float msafe = (mn == -INFINITY) ? 0.f : mn;
            float alpha = __expf(m_i[r] - msafe);   // -inf -> 0
            m_i[r] = mn;

            float rs = 0.f;
#pragma unroll
            for (int c = 0; c < 4; c++) {
                float p = __expf(s[r][c] - msafe);  // -inf -> 0
                s[r][c] = p;
                rs += p;
            }
            rs = allreduce_sum16(rs);
            l_i[r] = l_i[r] * alpha + rs;
#pragma unroll
            for (int c = 0; c < 4; c++) {
                o[r][c] *= alpha;
                Ps[(ty * 4 + r) * PP + tx * 4 + c] = s[r][c];
            }
        }
        __syncthreads();

        // O += P @ V  (contraction over j)
#pragma unroll 4
        for (int j = 0; j < 64; j++) {
            float4 vf = *(float4*)&Vs[j * PQ + tx * 4];
#pragma unroll
            for (int r = 0; r < 4; r++) {
                float pv = Ps[(ty * 4 + r) * PP + j];
                o[r][0] = fmaf(pv, vf.x, o[r][0]);
                o[r][1] = fmaf(pv, vf.y, o[r][1]);
                o[r][2] = fmaf(pv, vf.z, o[r][2]);
                o[r][3] = fmaf(pv, vf.w, o[r][3]);
            }
        }
    }

    // Write ctx in [b, s, h*hd] layout
    float* cbase = g_ctx + (size_t)b * S_ * DOUT + h * HD_;
#pragma unroll
    for (int r = 0; r < 4; r++) {
        int qg = q0 + ty * 4 + r;
        float inv = 1.f / l_i[r];
        float4 ov = make_float4(o[r][0] * inv, o[r][1] * inv,
                                o[r][2] * inv, o[r][3] * inv);
        *(float4*)(cbase + (size_t)qg * DOUT + tx * 4) = ov;
    }
}

// ---------------------------------------------------------------------------
extern "C" void kernel_launch(void* const* d_in, const int* in_sizes, int n_in,
                              void* d_out, int out_size)
{
    const float* x    = (const float*)d_in[0];
    const float* wqkv = (const float*)d_in[1];
    const float* wout = (const float*)d_in[2];
    const float* bout = (const float*)d_in[3];
    float* out = (float*)d_out;

    const int attn_smem = (3 * 64 * PQ + 64 * PP) * (int)sizeof(float);  // 68864 B
    cudaFuncSetAttribute(attn_kernel, cudaFuncAttributeMaxDynamicSharedMemorySize,
                         attn_smem);

    qkv_gemm<<<dim3(3 * DOUT / 64, (B_ * S_) / 128), 256>>>(x, wqkv);
    attn_kernel<<<dim3(S_ / 64, NH, B_), 256, attn_smem>>>();
    out_gemm<<<dim3(DOUT / 64, (B_ * S_) / 128), 256>>>(wout, bout, out);
}

// round 3
// speedup vs baseline: 1.7216x; 1.7216x over previous
#include <cuda_runtime.h>
#include <cuda_bf16.h>
#include <math.h>
#include <stdint.h>

#define B_    2
#define S_    2048
#define DIN   1024
#define DOUT  1024
#define NH    16
#define HD_   64
#define WIN   256
#define SCALE 0.125f

// Scratch (allocation-free rule: device globals)
__device__ float g_q[B_*NH*S_*HD_];    // [b,h,s,hd]
__device__ float g_k[B_*NH*S_*HD_];
__device__ float g_v[B_*NH*S_*HD_];
__device__ float g_ctx[B_*S_*DOUT];    // [b,s,h*hd]

// ===========================================================================
// bf16 3-term split GEMM via mma.sync (baseline sm_80+ PTX — no 'a' features)
// C[128x128] = A[128xK] @ B[128xK]^T (NT), K = 1024.
// 128 threads = 4 warps in 2x2 grid, warp tile 64x64.
// smem per stage: 4 tiles (Ahi,Alo,Bhi,Blo), each [8 kpairs][136 words pitch]
// ===========================================================================
#define KP_PITCH 136                       // 128 rows + 8 pad words
#define TILE_W   (8 * KP_PITCH)            // 1088 words per tile
#define STAGE_W  (4 * TILE_W)              // 4352 words per stage
#define GEMM_SMEM (2 * STAGE_W * 4)        // 34816 bytes

__device__ __forceinline__ void split2(float x, float y, uint32_t& hi, uint32_t& lo) {
    __nv_bfloat16 hx = __float2bfloat16(x);
    __nv_bfloat16 hy = __float2bfloat16(y);
    float rx = x - __bfloat162float(hx);
    float ry = y - __bfloat162float(hy);
    __nv_bfloat16 lx = __float2bfloat16(rx);
    __nv_bfloat16 ly = __float2bfloat16(ry);
    __nv_bfloat162 hv; hv.x = hx; hv.y = hy;
    __nv_bfloat162 lv; lv.x = lx; lv.y = ly;
    hi = *(uint32_t*)&hv;
    lo = *(uint32_t*)&lv;
}

__device__ __forceinline__ void mma_bf16(float c[4], const uint32_t a[4], const uint32_t b[2]) {
    asm volatile(
        "mma.sync.aligned.m16n8k16.row.col.f32.bf16.bf16.f32 "
        "{%0,%1,%2,%3}, {%4,%5,%6,%7}, {%8,%9}, {%0,%1,%2,%3};"
        : "+f"(c[0]), "+f"(c[1]), "+f"(c[2]), "+f"(c[3])
        : "r"(a[0]), "r"(a[1]), "r"(a[2]), "r"(a[3]), "r"(b[0]), "r"(b[1]));
}

// Load one k-step (16 floats of K) of A and B tiles, split hi/lo into smem.
__device__ __forceinline__ void stage_load(const float* __restrict__ Abase,
                                           const float* __restrict__ Bbase,
                                           int k0, uint32_t* st, int t)
{
    const int k4 = t & 3;        // which float4 along K
    const int r0 = t >> 2;       // base row
    uint32_t* Ahi = st;
    uint32_t* Alo = st + TILE_W;
    uint32_t* Bhi = st + 2 * TILE_W;
    uint32_t* Blo = st + 3 * TILE_W;
#pragma unroll
    for (int i = 0; i < 4; i++) {
        int row = r0 + i * 32;
        float4 v = *(const float4*)(Abase + (size_t)row * 1024 + k0 + k4 * 4);
        uint32_t h0, l0, h1, l1;
        split2(v.x, v.y, h0, l0);
        split2(v.z, v.w, h1, l1);
        Ahi[(2 * k4) * KP_PITCH + row]     = h0;
        Ahi[(2 * k4 + 1) * KP_PITCH + row] = h1;
        Alo[(2 * k4) * KP_PITCH + row]     = l0;
        Alo[(2 * k4 + 1) * KP_PITCH + row] = l1;

        float4 u = *(const float4*)(Bbase + (size_t)row * 1024 + k0 + k4 * 4);
        split2(u.x, u.y, h0, l0);
        split2(u.z, u.w, h1, l1);
        Bhi[(2 * k4) * KP_PITCH + row]     = h0;
        Bhi[(2 * k4 + 1) * KP_PITCH + row] = h1;
        Blo[(2 * k4) * KP_PITCH + row]     = l0;
        Blo[(2 * k4 + 1) * KP_PITCH + row] = l1;
    }
}

__device__ __forceinline__ void stage_compute(const uint32_t* st, int lane,
                                              int wm, int wn, float acc[4][8][4])
{
    const uint32_t* Ahi = st;
    const uint32_t* Alo = st + TILE_W;
    const uint32_t* Bhi = st + 2 * TILE_W;
    const uint32_t* Blo = st + 3 * TILE_W;
    const int g  = lane >> 2;
    const int tq = lane & 3;

    uint32_t ah[4][4], al[4][4], bh[8][2], bl[8][2];
#pragma unroll
    for (int i = 0; i < 4; i++) {
        int r = wm * 64 + i * 16 + g;
        ah[i][0] = Ahi[tq * KP_PITCH + r];
        ah[i][1] = Ahi[tq * KP_PITCH + r + 8];
        ah[i][2] = Ahi[(tq + 4) * KP_PITCH + r];
        ah[i][3] = Ahi[(tq + 4) * KP_PITCH + r + 8];
        al[i][0] = Alo[tq * KP_PITCH + r];
        al[i][1] = Alo[tq * KP_PITCH + r + 8];
        al[i][2] = Alo[(tq + 4) * KP_PITCH + r];
        al[i][3] = Alo[(tq + 4) * KP_PITCH + r + 8];
    }
#pragma unroll
    for (int j = 0; j < 8; j++) {
        int c = wn * 64 + j * 8 + g;
        bh[j][0] = Bhi[tq * KP_PITCH + c];
        bh[j][1] = Bhi[(tq + 4) * KP_PITCH + c];
        bl[j][0] = Blo[tq * KP_PITCH + c];
        bl[j][1] = Blo[(tq + 4) * KP_PITCH + c];
    }
    // pass 1: Ah * Bh
#pragma unroll
    for (int i = 0; i < 4; i++)
#pragma unroll
        for (int j = 0; j < 8; j++) mma_bf16(acc[i][j], ah[i], bh[j]);
    // pass 2: Al * Bh
#pragma unroll
    for (int i = 0; i < 4; i++)
#pragma unroll
        for (int j = 0; j < 8; j++) mma_bf16(acc[i][j], al[i], bh[j]);
    // pass 3: Ah * Bl
#pragma unroll
    for (int i = 0; i < 4; i++)
#pragma unroll
        for (int j = 0; j < 8; j++) mma_bf16(acc[i][j], ah[i], bl[j]);
}

__device__ __forceinline__ void gemm_mainloop(const float* __restrict__ A,
                                              const float* __restrict__ Bm,
                                              int m0, int n0, uint32_t* smw,
                                              float acc[4][8][4])
{
    const int t = threadIdx.x;
    const int lane = t & 31, wid = t >> 5;
    const int wm = wid >> 1, wn = wid & 1;
    const float* Abase = A  + (size_t)m0 * 1024;
    const float* Bbase = Bm + (size_t)n0 * 1024;

#pragma unroll
    for (int i = 0; i < 4; i++)
#pragma unroll
        for (int j = 0; j < 8; j++)
#pragma unroll
            for (int c = 0; c < 4; c++) acc[i][j][c] = 0.f;

    stage_load(Abase, Bbase, 0, smw, t);
    __syncthreads();
    for (int ks = 0; ks < 64; ks++) {
        const uint32_t* cur = smw + (ks & 1) * STAGE_W;
        if (ks < 63)
            stage_load(Abase, Bbase, (ks + 1) * 16, smw + ((ks + 1) & 1) * STAGE_W, t);
        stage_compute(cur, lane, wm, wn, acc);
        __syncthreads();
    }
}

// ===========================================================================
// QKV projection: C tile -> scatter into g_q/g_k/g_v [b,h,s,hd]
// ===========================================================================
__global__ __launch_bounds__(128, 1) void qkv_gemm_mma(const float* __restrict__ x,
                                                       const float* __restrict__ w)
{
    extern __shared__ uint32_t smw[];
    const int m0 = blockIdx.y * 128;
    const int n0 = blockIdx.x * 128;
    float acc[4][8][4];
    gemm_mainloop(x, w, m0, n0, smw, acc);

    const int t = threadIdx.x;
    const int lane = t & 31, wid = t >> 5;
    const int wm = wid >> 1, wn = wid & 1;
    const int g = lane >> 2, tq = lane & 3;

    const int which = n0 >> 10;  // 1024-boundaries are multiples of 128
    float* dst = (which == 0) ? g_q : (which == 1) ? g_k : g_v;

#pragma unroll
    for (int i = 0; i < 4; i++) {
        int m = m0 + wm * 64 + i * 16 + g;
        int b = m >> 11, s = m & (S_ - 1);
#pragma unroll
        for (int j = 0; j < 8; j++) {
            int nn = n0 + wn * 64 + j * 8;   // multiple of 8, no 64-crossing per tile
            int h  = (nn >> 6) & (NH - 1);
            int hd = (nn & 63) + 2 * tq;
            float* p = dst + (((size_t)(b * NH + h) * S_ + s) * HD_ + hd);
            *(float2*)p             = make_float2(acc[i][j][0], acc[i][j][1]);
            *(float2*)(p + 8 * HD_) = make_float2(acc[i][j][2], acc[i][j][3]);
        }
    }
}

// ===========================================================================
// Output projection: C tile + bias -> out [m][n]
// ===========================================================================
__global__ __launch_bounds__(128, 1) void out_gemm_mma(const float* __restrict__ w,
                                                       const float* __restrict__ bias,
                                                       float* __restrict__ out)
{
    extern __shared__ uint32_t smw[];
    const int m0 = blockIdx.y * 128;
    const int n0 = blockIdx.x * 128;
    float acc[4][8][4];
    gemm_mainloop(g_ctx, w, m0, n0, smw, acc);

    const int t = threadIdx.x;
    const int lane = t & 31, wid = t >> 5;
    const int wm = wid >> 1, wn = wid & 1;
    const int g = lane >> 2, tq = lane & 3;

#pragma unroll
    for (int i = 0; i < 4; i++) {
        int m = m0 + wm * 64 + i * 16 + g;
#pragma unroll
        for (int j = 0; j < 8; j++) {
            int nn = n0 + wn * 64 + j * 8 + 2 * tq;
            float2 bb = *(const float2*)(bias + nn);
            float* p = out + (size_t)m * DOUT + nn;
            *(float2*)p               = make_float2(acc[i][j][0] + bb.x, acc[i][j][1] + bb.y);
            *(float2*)(p + 8 * DOUT)  = make_float2(acc[i][j][2] + bb.x, acc[i][j][3] + bb.y);
        }
    }
}

// ===========================================================================
// Sliding-window attention, flash-style (unchanged from R1).
// ===========================================================================
#define PQ 68
#define PP 65

__device__ __forceinline__ float allreduce_max16(float v) {
#pragma unroll
    for (int off = 8; off; off >>= 1)
        v = fmaxf(v, __shfl_xor_sync(0xffffffffu, v, off, 16));
    return v;
}
__device__ __forceinline__ float allreduce_sum16(float v) {
#pragma unroll
    for (int off = 8; off; off >>= 1)
        v += __shfl_xor_sync(0xffffffffu, v, off, 16);
    return v;
}

__global__ __launch_bounds__(256) void attn_kernel()
{
    extern __shared__ float smf[];
    float* Qs = smf;
    float* Ks = Qs + 64 * PQ;
    float* Vs = Ks + 64 * PQ;
    float* Ps = Vs + 64 * PQ;

    const int q0 = blockIdx.x * 64;
    const int h  = blockIdx.y;
    const int b  = blockIdx.z;
    const int t  = threadIdx.x;
    const int ty = t >> 4;
    const int tx = t & 15;

    const size_t hb = (size_t)(b * NH + h) * S_ * HD_;
    const float* qbase = g_q + hb;
    const float* kbase = g_k + hb;
    const float* vbase = g_v + hb;

#pragma unroll
    for (int i2 = 0; i2 < 4; i2++) {
        int v   = t + i2 * 256;
        int row = v >> 4;
        int c4  = v & 15;
        float4 a = *(const float4*)(qbase + (size_t)(q0 + row) * HD_ + c4 * 4);
        Qs[(c4 * 4 + 0) * PQ + row] = a.x;
        Qs[(c4 * 4 + 1) * PQ + row] = a.y;
        Qs[(c4 * 4 + 2) * PQ + row] = a.z;
        Qs[(c4 * 4 + 3) * PQ + row] = a.w;
    }

    float o[4][4];
    float m_i[4], l_i[4];
#pragma unroll
    for (int r = 0; r < 4; r++) {
        m_i[r] = -INFINITY;
        l_i[r] = 0.f;
#pragma unroll
        for (int c = 0; c < 4; c++) o[r][c] = 0.f;
    }

    int kc_start = q0 - WIN; if (kc_start < 0) kc_start = 0;
    int kc_end   = q0 + 64 + WIN; if (kc_end > S_) kc_end = S_;

    for (int kc = kc_start; kc < kc_end; kc += 64) {
        __syncthreads();
#pragma unroll
        for (int i2 = 0; i2 < 4; i2++) {
            int v   = t + i2 * 256;
            int row = v >> 4;
            int c4  = v & 15;
            float4 a = *(const float4*)(kbase + (size_t)(kc + row) * HD_ + c4 * 4);
            Ks[(c4 * 4 + 0) * PQ + row] = a.x;
            Ks[(c4 * 4 + 1) * PQ + row] = a.y;
            Ks[(c4 * 4 + 2) * PQ + row] = a.z;
            Ks[(c4 * 4 + 3) * PQ + row] = a.w;
            float4 vv = *(const float4*)(vbase + (size_t)(kc + row) * HD_ + c4 * 4);
            *(float4*)&Vs[row * PQ + c4 * 4] = vv;
        }
        __syncthreads();

        float s[4][4];
#pragma unroll
        for (int r = 0; r < 4; r++)
#pragma unroll
            for (int c = 0; c < 4; c++) s[r][c] = 0.f;

#pragma unroll 8
        for (int d = 0; d < 64; d++) {
            float4 qf = *(float4*)&Qs[d * PQ + ty * 4];
            float4 kf = *(float4*)&Ks[d * PQ + tx * 4];
            float qv[4] = {qf.x, qf.y, qf.z, qf.w};
            float kv[4] = {kf.x, kf.y, kf.z, kf.w};
#pragma unroll
            for (int r = 0; r < 4; r++)
#pragma unroll
                for (int c = 0; c < 4; c++) s[r][c] = fmaf(qv[r], kv[c], s[r][c]);
        }

#pragma unroll
        for (int r = 0; r < 4; r++) {
            int qg = q0 + ty * 4 + r;
            float mc = -INFINITY;
#pragma unroll
            for (int c = 0; c < 4; c++) {
                int kg = kc + tx * 4 + c;
                int dd = qg - kg; if (dd < 0) dd = -dd;
                s[r][c] = (dd <= WIN) ? s[r][c] * SCALE : -INFINITY;
                mc = fmaxf(mc, s[r][c]);
            }
            mc = allreduce_max16(mc);

            float mn    = fmaxf(m_i[r], mc);
            float msafe = (mn == -INFINITY) ? 0.f : mn;
            float alpha = __expf(m_i[r] - msafe);
            m_i[r] = mn;

            float rs = 0.f;
#pragma unroll
            for (int c = 0; c < 4; c++) {
                float p = __expf(s[r][c] - msafe);
                s[r][c] = p;
                rs += p;
            }
            rs = allreduce_sum16(rs);
            l_i[r] = l_i[r] * alpha + rs;
#pragma unroll
            for (int c = 0; c < 4; c++) {
                o[r][c] *= alpha;
                Ps[(ty * 4 + r) * PP + tx * 4 + c] = s[r][c];
            }
        }
        __syncthreads();

#pragma unroll 4
        for (int j = 0; j < 64; j++) {
            float4 vf = *(float4*)&Vs[j * PQ + tx * 4];
#pragma unroll
            for (int r = 0; r < 4; r++) {
                float pv = Ps[(ty * 4 + r) * PP + j];
                o[r][0] = fmaf(pv, vf.x, o[r][0]);
                o[r][1] = fmaf(pv, vf.y, o[r][1]);
                o[r][2] = fmaf(pv, vf.z, o[r][2]);
                o[r][3] = fmaf(pv, vf.w, o[r][3]);
            }
        }
    }

    float* cbase = g_ctx + (size_t)b * S_ * DOUT + h * HD_;
#pragma unroll
    for (int r = 0; r < 4; r++) {
        int qg = q0 + ty * 4 + r;
        float inv = 1.f / l_i[r];
        float4 ov = make_float4(o[r][0] * inv, o[r][1] * inv,
                                o[r][2] * inv, o[r][3] * inv);
        *(float4*)(cbase + (size_t)qg * DOUT + tx * 4) = ov;
    }
}

// ===========================================================================
extern "C" void kernel_launch(void* const* d_in, const int* in_sizes, int n_in,
                              void* d_out, int out_size)
{
    const float* x    = (const float*)d_in[0];
    const float* wqkv = (const float*)d_in[1];
    const float* wout = (const float*)d_in[2];
    const float* bout = (const float*)d_in[3];
    float* out = (float*)d_out;

    const int attn_smem = (3 * 64 * PQ + 64 * PP) * (int)sizeof(float);

    cudaFuncSetAttribute(attn_kernel, cudaFuncAttributeMaxDynamicSharedMemorySize, attn_smem);

    qkv_gemm_mma<<<dim3(3 * DOUT / 128, (B_ * S_) / 128), 128, GEMM_SMEM>>>(x, wqkv);
    attn_kernel<<<dim3(S_ / 64, NH, B_), 256, attn_smem>>>();
    out_gemm_mma<<<dim3(DOUT / 128, (B_ * S_) / 128), 128, GEMM_SMEM>>>(wout, bout, out);
}

// round 4
// speedup vs baseline: 2.1289x; 1.2366x over previous
#include <cuda_runtime.h>
#include <cuda_bf16.h>
#include <math.h>
#include <stdint.h>

#define B_    2
#define S_    2048
#define DIN   1024
#define DOUT  1024
#define NH    16
#define HD_   64
#define WIN   256
#define SCALE 0.125f

// Scratch (allocation-free rule: device globals)
__device__ float g_q[B_*NH*S_*HD_];    // [b,h,s,hd]
__device__ float g_k[B_*NH*S_*HD_];
__device__ float g_v[B_*NH*S_*HD_];
__device__ float g_ctx[B_*S_*DOUT];    // [b,s,h*hd]

// ===========================================================================
// Common helpers
// ===========================================================================
__device__ __forceinline__ void split2(float x, float y, uint32_t& hi, uint32_t& lo) {
    __nv_bfloat16 hx = __float2bfloat16(x);
    __nv_bfloat16 hy = __float2bfloat16(y);
    float rx = x - __bfloat162float(hx);
    float ry = y - __bfloat162float(hy);
    __nv_bfloat16 lx = __float2bfloat16(rx);
    __nv_bfloat16 ly = __float2bfloat16(ry);
    __nv_bfloat162 hv; hv.x = hx; hv.y = hy;
    __nv_bfloat162 lv; lv.x = lx; lv.y = ly;
    hi = *(uint32_t*)&hv;
    lo = *(uint32_t*)&lv;
}

__device__ __forceinline__ void mma_bf16(float c[4], const uint32_t a[4], const uint32_t b[2]) {
    asm volatile(
        "mma.sync.aligned.m16n8k16.row.col.f32.bf16.bf16.f32 "
        "{%0,%1,%2,%3}, {%4,%5,%6,%7}, {%8,%9}, {%0,%1,%2,%3};"
        : "+f"(c[0]), "+f"(c[1]), "+f"(c[2]), "+f"(c[3])
        : "r"(a[0]), "r"(a[1]), "r"(a[2]), "r"(a[3]), "r"(b[0]), "r"(b[1]));
}

// ===========================================================================
// bf16 3-term split GEMM: C[128x128] = A[128xK] @ B[128xK]^T (NT), K=1024.
// 256 threads = 8 warps in 2(M)x4(N) grid, warp tile 64x32.
// ===========================================================================
#define KP_PITCH 136
#define TILE_W   (8 * KP_PITCH)
#define STAGE_W  (4 * TILE_W)
#define GEMM_SMEM (2 * STAGE_W * 4)

__device__ __forceinline__ void stage_load(const float* __restrict__ Abase,
                                           const float* __restrict__ Bbase,
                                           int k0, uint32_t* st, int t)
{
    const int k4 = t & 3;
    const int r0 = t >> 2;    // 0..63
    uint32_t* Ahi = st;
    uint32_t* Alo = st + TILE_W;
    uint32_t* Bhi = st + 2 * TILE_W;
    uint32_t* Blo = st + 3 * TILE_W;
#pragma unroll
    for (int i = 0; i < 2; i++) {
        int row = r0 + i * 64;
        float4 v = *(const float4*)(Abase + (size_t)row * 1024 + k0 + k4 * 4);
        uint32_t h0, l0, h1, l1;
        split2(v.x, v.y, h0, l0);
        split2(v.z, v.w, h1, l1);
        Ahi[(2 * k4) * KP_PITCH + row]     = h0;
        Ahi[(2 * k4 + 1) * KP_PITCH + row] = h1;
        Alo[(2 * k4) * KP_PITCH + row]     = l0;
        Alo[(2 * k4 + 1) * KP_PITCH + row] = l1;

        float4 u = *(const float4*)(Bbase + (size_t)row * 1024 + k0 + k4 * 4);
        split2(u.x, u.y, h0, l0);
        split2(u.z, u.w, h1, l1);
        Bhi[(2 * k4) * KP_PITCH + row]     = h0;
        Bhi[(2 * k4 + 1) * KP_PITCH + row] = h1;
        Blo[(2 * k4) * KP_PITCH + row]     = l0;
        Blo[(2 * k4 + 1) * KP_PITCH + row] = l1;
    }
}

__device__ __forceinline__ void stage_compute(const uint32_t* st, int lane,
                                              int wm, int wn, float acc[4][4][4])
{
    const uint32_t* Ahi = st;
    const uint32_t* Alo = st + TILE_W;
    const uint32_t* Bhi = st + 2 * TILE_W;
    const uint32_t* Blo = st + 3 * TILE_W;
    const int g  = lane >> 2;
    const int tq = lane & 3;

    uint32_t ah[4][4], al[4][4], bh[4][2], bl[4][2];
#pragma unroll
    for (int i = 0; i < 4; i++) {
        int r = wm * 64 + i * 16 + g;
        ah[i][0] = Ahi[tq * KP_PITCH + r];
        ah[i][1] = Ahi[tq * KP_PITCH + r + 8];
        ah[i][2] = Ahi[(tq + 4) * KP_PITCH + r];
        ah[i][3] = Ahi[(tq + 4) * KP_PITCH + r + 8];
        al[i][0] = Alo[tq * KP_PITCH + r];
        al[i][1] = Alo[tq * KP_PITCH + r + 8];
        al[i][2] = Alo[(tq + 4) * KP_PITCH + r];
        al[i][3] = Alo[(tq + 4) * KP_PITCH + r + 8];
    }
#pragma unroll
    for (int j = 0; j < 4; j++) {
        int c = wn * 32 + j * 8 + g;
        bh[j][0] = Bhi[tq * KP_PITCH + c];
        bh[j][1] = Bhi[(tq + 4) * KP_PITCH + c];
        bl[j][0] = Blo[tq * KP_PITCH + c];
        bl[j][1] = Blo[(tq + 4) * KP_PITCH + c];
    }
#pragma unroll
    for (int i = 0; i < 4; i++)
#pragma unroll
        for (int j = 0; j < 4; j++) mma_bf16(acc[i][j], ah[i], bh[j]);
#pragma unroll
    for (int i = 0; i < 4; i++)
#pragma unroll
        for (int j = 0; j < 4; j++) mma_bf16(acc[i][j], al[i], bh[j]);
#pragma unroll
    for (int i = 0; i < 4; i++)
#pragma unroll
        for (int j = 0; j < 4; j++) mma_bf16(acc[i][j], ah[i], bl[j]);
}

__device__ __forceinline__ void gemm_mainloop(const float* __restrict__ A,
                                              const float* __restrict__ Bm,
                                              int m0, int n0, uint32_t* smw,
                                              float acc[4][4][4])
{
    const int t = threadIdx.x;
    const int lane = t & 31, wid = t >> 5;
    const int wm = wid >> 2, wn = wid & 3;
    const float* Abase = A  + (size_t)m0 * 1024;
    const float* Bbase = Bm + (size_t)n0 * 1024;

#pragma unroll
    for (int i = 0; i < 4; i++)
#pragma unroll
        for (int j = 0; j < 4; j++)
#pragma unroll
            for (int c = 0; c < 4; c++) acc[i][j][c] = 0.f;

    stage_load(Abase, Bbase, 0, smw, t);
    __syncthreads();
    for (int ks = 0; ks < 64; ks++) {
        const uint32_t* cur = smw + (ks & 1) * STAGE_W;
        if (ks < 63)
            stage_load(Abase, Bbase, (ks + 1) * 16, smw + ((ks + 1) & 1) * STAGE_W, t);
        stage_compute(cur, lane, wm, wn, acc);
        __syncthreads();
    }
}

__global__ __launch_bounds__(256, 1) void qkv_gemm_mma(const float* __restrict__ x,
                                                       const float* __restrict__ w)
{
    extern __shared__ uint32_t smw[];
    const int m0 = blockIdx.y * 128;
    const int n0 = blockIdx.x * 128;
    float acc[4][4][4];
    gemm_mainloop(x, w, m0, n0, smw, acc);

    const int t = threadIdx.x;
    const int lane = t & 31, wid = t >> 5;
    const int wm = wid >> 2, wn = wid & 3;
    const int g = lane >> 2, tq = lane & 3;

    const int which = n0 >> 10;
    float* dst = (which == 0) ? g_q : (which == 1) ? g_k : g_v;

#pragma unroll
    for (int i = 0; i < 4; i++) {
        int m = m0 + wm * 64 + i * 16 + g;
        int b = m >> 11, s = m & (S_ - 1);
#pragma unroll
        for (int j = 0; j < 4; j++) {
            int nn = n0 + wn * 32 + j * 8;
            int h  = (nn >> 6) & (NH - 1);
            int hd = (nn & 63) + 2 * tq;
            float* p = dst + (((size_t)(b * NH + h) * S_ + s) * HD_ + hd);
            *(float2*)p             = make_float2(acc[i][j][0], acc[i][j][1]);
            *(float2*)(p + 8 * HD_) = make_float2(acc[i][j][2], acc[i][j][3]);
        }
    }
}

__global__ __launch_bounds__(256, 1) void out_gemm_mma(const float* __restrict__ w,
                                                       const float* __restrict__ bias,
                                                       float* __restrict__ out)
{
    extern __shared__ uint32_t smw[];
    const int m0 = blockIdx.y * 128;
    const int n0 = blockIdx.x * 128;
    float acc[4][4][4];
    gemm_mainloop(g_ctx, w, m0, n0, smw, acc);

    const int t = threadIdx.x;
    const int lane = t & 31, wid = t >> 5;
    const int wm = wid >> 2, wn = wid & 3;
    const int g = lane >> 2, tq = lane & 3;

#pragma unroll
    for (int i = 0; i < 4; i++) {
        int m = m0 + wm * 64 + i * 16 + g;
#pragma unroll
        for (int j = 0; j < 4; j++) {
            int nn = n0 + wn * 32 + j * 8 + 2 * tq;
            float2 bb = *(const float2*)(bias + nn);
            float* p = out + (size_t)m * DOUT + nn;
            *(float2*)p              = make_float2(acc[i][j][0] + bb.x, acc[i][j][1] + bb.y);
            *(float2*)(p + 8 * DOUT) = make_float2(acc[i][j][2] + bb.x, acc[i][j][3] + bb.y);
        }
    }
}

// ===========================================================================
// Tensor-core sliding-window attention (flash-mma).
// Block = 64 queries of one (b,h); 128 threads = 4 warps; warp w owns query
// rows 16w..16w+15. Q fragments live in registers for all chunks.
// Smem: K and V chunk tiles in bf16 hi/lo, [row][hd], pitch 72 bf16 (36 words).
// bank(frag LDS.32) = 4g+tq -> conflict-free.
// ===========================================================================
#define AP 36                        // words per row (72 bf16)
#define AT_TILE_W (64 * AP)          // 2304 words per tile
#define ATTN_SMEM (4 * AT_TILE_W * 4)  // 36864 bytes

__device__ __forceinline__ void fill_hilo(const float* __restrict__ src,
                                          uint32_t* hi, uint32_t* lo, int t)
{
    int row = t >> 1, hs = t & 1;
    const float4* gp = (const float4*)(src + (size_t)row * HD_ + hs * 32);
    uint32_t* hrow = hi + row * AP + hs * 16;
    uint32_t* lrow = lo + row * AP + hs * 16;
#pragma unroll
    for (int j = 0; j < 8; j++) {
        float4 v = gp[j];
        uint32_t h01, l01, h23, l23;
        split2(v.x, v.y, h01, l01);
        split2(v.z, v.w, h23, l23);
        hrow[2 * j]     = h01;
        hrow[2 * j + 1] = h23;
        lrow[2 * j]     = l01;
        lrow[2 * j + 1] = l23;
    }
}

__global__ __launch_bounds__(128, 2) void attn_mma()
{
    extern __shared__ uint32_t sw[];
    uint32_t* Khi = sw;
    uint32_t* Klo = sw + AT_TILE_W;
    uint32_t* Vhi = sw + 2 * AT_TILE_W;
    uint32_t* Vlo = sw + 3 * AT_TILE_W;

    const int t    = threadIdx.x;
    const int lane = t & 31;
    const int w    = t >> 5;
    const int g    = lane >> 2;
    const int tq   = lane & 3;

    const int q0 = blockIdx.x * 64;
    const int h  = blockIdx.y;
    const int b  = blockIdx.z;

    const size_t hb = (size_t)(b * NH + h) * S_ * HD_;
    const float* qbase = g_q + hb;
    const float* kbase = g_k + hb;
    const float* vbase = g_v + hb;

    // --- Stage Q through smem, grab fragments into registers ---
    fill_hilo(qbase + (size_t)q0 * HD_, Khi, Klo, t);
    __syncthreads();

    uint32_t qh[4][4], ql[4][4];
    {
        int r = 16 * w + g;
#pragma unroll
        for (int ks = 0; ks < 4; ks++) {
            int base = r * AP + 8 * ks + tq;
            qh[ks][0] = Khi[base];
            qh[ks][1] = Khi[base + 8 * AP];
            qh[ks][2] = Khi[base + 4];
            qh[ks][3] = Khi[base + 8 * AP + 4];
            ql[ks][0] = Klo[base];
            ql[ks][1] = Klo[base + 8 * AP];
            ql[ks][2] = Klo[base + 4];
            ql[ks][3] = Klo[base + 8 * AP + 4];
        }
    }

    float oacc[8][4];
#pragma unroll
    for (int j = 0; j < 8; j++)
#pragma unroll
        for (int c = 0; c < 4; c++) oacc[j][c] = 0.f;
    float m_[2] = {-INFINITY, -INFINITY};
    float l_[2] = {0.f, 0.f};

    int kc_start = q0 - WIN; if (kc_start < 0) kc_start = 0;
    int kc_end   = q0 + 64 + WIN; if (kc_end > S_) kc_end = S_;

    const int row0 = q0 + 16 * w + g;

    for (int kc = kc_start; kc < kc_end; kc += 64) {
        __syncthreads();   // previous chunk compute done before refill
        fill_hilo(kbase + (size_t)kc * HD_, Khi, Klo, t);
        fill_hilo(vbase + (size_t)kc * HD_, Vhi, Vlo, t);
        __syncthreads();

        // ---- S = Q @ K^T (3-pass) ----
        float sacc[8][4];
#pragma unroll
        for (int j = 0; j < 8; j++)
#pragma unroll
            for (int c = 0; c < 4; c++) sacc[j][c] = 0.f;

#pragma unroll
        for (int ks = 0; ks < 4; ks++) {
#pragma unroll
            for (int j = 0; j < 8; j++) {
                int base = (8 * j + g) * AP + 8 * ks + tq;
                uint32_t bh[2] = {Khi[base], Khi[base + 4]};
                uint32_t bl[2] = {Klo[base], Klo[base + 4]};
                mma_bf16(sacc[j], qh[ks], bh);
                mma_bf16(sacc[j], ql[ks], bh);
                mma_bf16(sacc[j], qh[ks], bl);
            }
        }

        // ---- mask + online softmax (rows g and g+8) ----
#pragma unroll
        for (int half = 0; half < 2; half++) {
            int row = row0 + 8 * half;
            float mx = -INFINITY;
#pragma unroll
            for (int j = 0; j < 8; j++) {
                int col = kc + 8 * j + 2 * tq;
                float v0 = sacc[j][2 * half];
                float v1 = sacc[j][2 * half + 1];
                int d0 = row - col;     d0 = d0 < 0 ? -d0 : d0;
                int d1 = row - col - 1; d1 = d1 < 0 ? -d1 : d1;
                v0 = (d0 <= WIN) ? v0 * SCALE : -INFINITY;
                v1 = (d1 <= WIN) ? v1 * SCALE : -INFINITY;
                sacc[j][2 * half]     = v0;
                sacc[j][2 * half + 1] = v1;
                mx = fmaxf(mx, fmaxf(v0, v1));
            }
            mx = fmaxf(mx, __shfl_xor_sync(0xffffffffu, mx, 1, 4));
            mx = fmaxf(mx, __shfl_xor_sync(0xffffffffu, mx, 2, 4));

            float mn    = fmaxf(m_[half], mx);
            float msafe = (mn == -INFINITY) ? 0.f : mn;
            float alpha = __expf(m_[half] - msafe);
            m_[half] = mn;

            float rs = 0.f;
#pragma unroll
            for (int j = 0; j < 8; j++) {
                float p0 = __expf(sacc[j][2 * half]     - msafe);
                float p1 = __expf(sacc[j][2 * half + 1] - msafe);
                sacc[j][2 * half]     = p0;
                sacc[j][2 * half + 1] = p1;
                rs += p0 + p1;
            }
            rs += __shfl_xor_sync(0xffffffffu, rs, 1, 4);
            rs += __shfl_xor_sync(0xffffffffu, rs, 2, 4);
            l_[half] = l_[half] * alpha + rs;
#pragma unroll
            for (int j = 0; j < 8; j++) {
                oacc[j][2 * half]     *= alpha;
                oacc[j][2 * half + 1] *= alpha;
            }
        }

        // ---- O += P @ V (3-pass); P frags built from sacc registers ----
        const unsigned short* vhs = (const unsigned short*)Vhi;
        const unsigned short* vls = (const unsigned short*)Vlo;
#pragma unroll
        for (int kp = 0; kp < 4; kp++) {
            uint32_t ph[4], pl[4];
            split2(sacc[2 * kp][0],     sacc[2 * kp][1],     ph[0], pl[0]);
            split2(sacc[2 * kp][2],     sacc[2 * kp][3],     ph[1], pl[1]);
            split2(sacc[2 * kp + 1][0], sacc[2 * kp + 1][1], ph[2], pl[2]);
            split2(sacc[2 * kp + 1][2], sacc[2 * kp + 1][3], ph[3], pl[3]);

            int key0 = 16 * kp + 2 * tq;
#pragma unroll
            for (int j = 0; j < 8; j++) {
                int hd = 8 * j + g;
                uint32_t vh[2], vl[2];
                vh[0] = (uint32_t)vhs[key0 * 72 + hd]       | ((uint32_t)vhs[(key0 + 1) * 72 + hd] << 16);
                vh[1] = (uint32_t)vhs[(key0 + 8) * 72 + hd] | ((uint32_t)vhs[(key0 + 9) * 72 + hd] << 16);
                vl[0] = (uint32_t)vls[key0 * 72 + hd]       | ((uint32_t)vls[(key0 + 1) * 72 + hd] << 16);
                vl[1] = (uint32_t)vls[(key0 + 8) * 72 + hd] | ((uint32_t)vls[(key0 + 9) * 72 + hd] << 16);
                mma_bf16(oacc[j], ph, vh);
                mma_bf16(oacc[j], pl, vh);
                mma_bf16(oacc[j], ph, vl);
            }
        }
    }

    // ---- finalize: O / l -> g_ctx [b][s][h*64+hd] ----
    float rl0 = 1.f / l_[0];
    float rl1 = 1.f / l_[1];
    float* c0 = g_ctx + ((size_t)b * S_ + row0) * DOUT + h * HD_;
    float* c1 = c0 + 8 * DOUT;   // row0 + 8
#pragma unroll
    for (int j = 0; j < 8; j++) {
        int hd = 8 * j + 2 * tq;
        *(float2*)(c0 + hd) = make_float2(oacc[j][0] * rl0, oacc[j][1] * rl0);
        *(float2*)(c1 + hd) = make_float2(oacc[j][2] * rl1, oacc[j][3] * rl1);
    }
}

// ===========================================================================
extern "C" void kernel_launch(void* const* d_in, const int* in_sizes, int n_in,
                              void* d_out, int out_size)
{
    const float* x    = (const float*)d_in[0];
    const float* wqkv = (const float*)d_in[1];
    const float* wout = (const float*)d_in[2];
    const float* bout = (const float*)d_in[3];
    float* out = (float*)d_out;

    qkv_gemm_mma<<<dim3(3 * DOUT / 128, (B_ * S_) / 128), 256, GEMM_SMEM>>>(x, wqkv);
    attn_mma<<<dim3(S_ / 64, NH, B_), 128, ATTN_SMEM>>>();
    out_gemm_mma<<<dim3(DOUT / 128, (B_ * S_) / 128), 256, GEMM_SMEM>>>(wout, bout, out);
}

// round 5
// speedup vs baseline: 2.2174x; 1.0416x over previous
#include <cuda_runtime.h>
#include <cuda_bf16.h>
#include <math.h>
#include <stdint.h>

#define B_    2
#define S_    2048
#define DIN   1024
#define DOUT  1024
#define NH    16
#define HD_   64
#define WIN   256
#define SCALE 0.125f

#define NQKV (B_*NH*S_*HD_)     // 4.19M
#define NX   (B_*S_*DIN)        // 4.19M

// Scratch (device globals; allocation-free rule)
__device__ __align__(16) __nv_bfloat16 gx_h[NX],  gx_l[NX];
__device__ __align__(16) __nv_bfloat16 gwq_h[3*DOUT*DIN], gwq_l[3*DOUT*DIN];
__device__ __align__(16) __nv_bfloat16 gwo_h[DOUT*DOUT],  gwo_l[DOUT*DOUT];
__device__ __align__(16) __nv_bfloat16 gq_h[NQKV], gq_l[NQKV];
__device__ __align__(16) __nv_bfloat16 gk_h[NQKV], gk_l[NQKV];
__device__ __align__(16) __nv_bfloat16 gv_h[NQKV], gv_l[NQKV];
__device__ __align__(16) __nv_bfloat16 gc_h[B_*S_*DOUT], gc_l[B_*S_*DOUT];

// ===========================================================================
// Helpers
// ===========================================================================
__device__ __forceinline__ void split2(float x, float y, uint32_t& hi, uint32_t& lo) {
    __nv_bfloat16 hx = __float2bfloat16(x);
    __nv_bfloat16 hy = __float2bfloat16(y);
    float rx = x - __bfloat162float(hx);
    float ry = y - __bfloat162float(hy);
    __nv_bfloat16 lx = __float2bfloat16(rx);
    __nv_bfloat16 ly = __float2bfloat16(ry);
    __nv_bfloat162 hv; hv.x = hx; hv.y = hy;
    __nv_bfloat162 lv; lv.x = lx; lv.y = ly;
    hi = *(uint32_t*)&hv;
    lo = *(uint32_t*)&lv;
}

__device__ __forceinline__ void mma_bf16(float c[4], const uint32_t a[4], const uint32_t b[2]) {
    asm volatile(
        "mma.sync.aligned.m16n8k16.row.col.f32.bf16.bf16.f32 "
        "{%0,%1,%2,%3}, {%4,%5,%6,%7}, {%8,%9}, {%0,%1,%2,%3};"
        : "+f"(c[0]), "+f"(c[1]), "+f"(c[2]), "+f"(c[3])
        : "r"(a[0]), "r"(a[1]), "r"(a[2]), "r"(a[3]), "r"(b[0]), "r"(b[1]));
}

#define CPA16(dst, src) asm volatile("cp.async.cg.shared.global [%0], [%1], 16;" :: "r"(dst), "l"(src))
#define CPC()  asm volatile("cp.async.commit_group;" ::: "memory")
#define CPW(n) asm volatile("cp.async.wait_group %0;" :: "n"(n) : "memory")

#define LDSM4(d0,d1,d2,d3,a) \
    asm volatile("ldmatrix.sync.aligned.m8n8.x4.shared.b16 {%0,%1,%2,%3}, [%4];" \
                 : "=r"(d0),"=r"(d1),"=r"(d2),"=r"(d3) : "r"(a))
#define LDSM4T(d0,d1,d2,d3,a) \
    asm volatile("ldmatrix.sync.aligned.m8n8.x4.trans.shared.b16 {%0,%1,%2,%3}, [%4];" \
                 : "=r"(d0),"=r"(d1),"=r"(d2),"=r"(d3) : "r"(a))

__device__ __forceinline__ uint32_t scvta(const void* p) {
    return (uint32_t)__cvta_generic_to_shared(p);
}

// ===========================================================================
// Elementwise split: fp32 -> bf16 hi/lo
// ===========================================================================
__global__ void split_kernel(const float4* __restrict__ src, uint2* __restrict__ hi,
                             uint2* __restrict__ lo, int n4)
{
    int i = blockIdx.x * 256 + threadIdx.x;
    if (i < n4) {
        float4 v = src[i];
        uint32_t h0, l0, h1, l1;
        split2(v.x, v.y, h0, l0);
        split2(v.z, v.w, h1, l1);
        hi[i] = make_uint2(h0, h1);
        lo[i] = make_uint2(l0, l1);
    }
}

// ===========================================================================
// GEMM: C[128x128] = A[128xK] @ B[128xK]^T, K=1024, bf16 3-pass.
// 256 threads = 8 warps (2M x 4N), warp tile 64x32, BK=32, 3-stage cp.async.
// ===========================================================================
#define PRB      80                  // bytes per smem row (64 payload + 16 pad)
#define GTILE_B  (128 * PRB)         // 10240
#define GSTAGE_B (4 * GTILE_B)       // 40960 (Ahi,Alo,Bhi,Blo)
#define GEMM_SMEM (3 * GSTAGE_B)     // 122880

__device__ __forceinline__ void gstage(const __nv_bfloat16* Ah, const __nv_bfloat16* Al,
                                       const __nv_bfloat16* Bh, const __nv_bfloat16* Bl,
                                       int k0, uint32_t sb, int t)
{
    const int row = t >> 2, c = t & 3;
    const __nv_bfloat16* srcs[4] = {Ah, Al, Bh, Bl};
#pragma unroll
    for (int tile = 0; tile < 4; tile++) {
#pragma unroll
        for (int i = 0; i < 2; i++) {
            int r = row + 64 * i;
            const void* g = srcs[tile] + (size_t)r * 1024 + k0 + c * 8;
            uint32_t d = sb + tile * GTILE_B + r * PRB + c * 16;
            CPA16(d, g);
        }
    }
}

__device__ __forceinline__ void gcompute(uint32_t sb, int lane, int wm, int wn,
                                         float acc[4][4][4])
{
#pragma unroll
    for (int kc = 0; kc < 2; kc++) {
        uint32_t ah[4][4], al[4][4], bh[4][2], bl[4][2];
#pragma unroll
        for (int i = 0; i < 4; i++) {
            int r = wm * 64 + i * 16 + (lane & 15);
            uint32_t a = sb + r * PRB + kc * 32 + (lane >> 4) * 16;
            LDSM4(ah[i][0], ah[i][1], ah[i][2], ah[i][3], a);
            LDSM4(al[i][0], al[i][1], al[i][2], al[i][3], a + GTILE_B);
        }
#pragma unroll
        for (int jp = 0; jp < 2; jp++) {
            int r = wn * 32 + jp * 16 + (lane >> 4) * 8 + (lane & 7);
            uint32_t a = sb + 2 * GTILE_B + r * PRB + kc * 32 + ((lane >> 3) & 1) * 16;
            LDSM4(bh[2*jp][0], bh[2*jp][1], bh[2*jp+1][0], bh[2*jp+1][1], a);
            LDSM4(bl[2*jp][0], bl[2*jp][1], bl[2*jp+1][0], bl[2*jp+1][1], a + GTILE_B);
        }
#pragma unroll
        for (int i = 0; i < 4; i++)
#pragma unroll
            for (int j = 0; j < 4; j++) mma_bf16(acc[i][j], ah[i], bh[j]);
#pragma unroll
        for (int i = 0; i < 4; i++)
#pragma unroll
            for (int j = 0; j < 4; j++) mma_bf16(acc[i][j], al[i], bh[j]);
#pragma unroll
        for (int i = 0; i < 4; i++)
#pragma unroll
            for (int j = 0; j < 4; j++) mma_bf16(acc[i][j], ah[i], bl[j]);
    }
}

__device__ __forceinline__ void gemm_main(const __nv_bfloat16* Ah, const __nv_bfloat16* Al,
                                          const __nv_bfloat16* Bh, const __nv_bfloat16* Bl,
                                          uint32_t sb, float acc[4][4][4])
{
    const int t = threadIdx.x;
    const int lane = t & 31, wid = t >> 5;
    const int wm = wid >> 2, wn = wid & 3;

#pragma unroll
    for (int i = 0; i < 4; i++)
#pragma unroll
        for (int j = 0; j < 4; j++)
#pragma unroll
            for (int c = 0; c < 4; c++) acc[i][j][c] = 0.f;

    gstage(Ah, Al, Bh, Bl, 0,  sb, t);             CPC();
    gstage(Ah, Al, Bh, Bl, 32, sb + GSTAGE_B, t);  CPC();

    for (int ks = 0; ks < 32; ks++) {
        CPW(1);
        __syncthreads();
        if (ks < 30)
            gstage(Ah, Al, Bh, Bl, (ks + 2) * 32, sb + ((ks + 2) % 3) * GSTAGE_B, t);
        CPC();   // always commit so group numbering stays uniform
        gcompute(sb + (ks % 3) * GSTAGE_B, lane, wm, wn, acc);
    }
}

__global__ __launch_bounds__(256, 1) void qkv_gemm_k()
{
    extern __shared__ char smg[];
    uint32_t sb = scvta(smg);
    const int m0 = blockIdx.y * 128;
    const int n0 = blockIdx.x * 128;

    float acc[4][4][4];
    gemm_main(gx_h + (size_t)m0 * 1024, gx_l + (size_t)m0 * 1024,
              gwq_h + (size_t)n0 * 1024, gwq_l + (size_t)n0 * 1024, sb, acc);

    const int t = threadIdx.x;
    const int lane = t & 31, wid = t >> 5;
    const int wm = wid >> 2, wn = wid & 3;
    const int g = lane >> 2, tq = lane & 3;

    const int which = n0 >> 10;
    __nv_bfloat16* dh = (which == 0) ? gq_h : (which == 1) ? gk_h : gv_h;
    __nv_bfloat16* dl = (which == 0) ? gq_l : (which == 1) ? gk_l : gv_l;

#pragma unroll
    for (int i = 0; i < 4; i++) {
        int m = m0 + wm * 64 + i * 16 + g;
        int b = m >> 11, s = m & (S_ - 1);
#pragma unroll
        for (int j = 0; j < 4; j++) {
            int nn = n0 + wn * 32 + j * 8;
            int h  = (nn >> 6) & (NH - 1);
            int hd = (nn & 63) + 2 * tq;
            size_t idx = (((size_t)(b * NH + h) * S_ + s) * HD_ + hd);
            uint32_t hw, lw;
            split2(acc[i][j][0], acc[i][j][1], hw, lw);
            *(uint32_t*)(dh + idx) = hw;
            *(uint32_t*)(dl + idx) = lw;
            split2(acc[i][j][2], acc[i][j][3], hw, lw);
            *(uint32_t*)(dh + idx + 8 * HD_) = hw;
            *(uint32_t*)(dl + idx + 8 * HD_) = lw;
        }
    }
}

__global__ __launch_bounds__(256, 1) void out_gemm_k(const float* __restrict__ bias,
                                                     float* __restrict__ out)
{
    extern __shared__ char smg[];
    uint32_t sb = scvta(smg);
    const int m0 = blockIdx.y * 128;
    const int n0 = blockIdx.x * 128;

    float acc[4][4][4];
    gemm_main(gc_h + (size_t)m0 * 1024, gc_l + (size_t)m0 * 1024,
              gwo_h + (size_t)n0 * 1024, gwo_l + (size_t)n0 * 1024, sb, acc);

    const int t = threadIdx.x;
    const int lane = t & 31, wid = t >> 5;
    const int wm = wid >> 2, wn = wid & 3;
    const int g = lane >> 2, tq = lane & 3;

#pragma unroll
    for (int i = 0; i < 4; i++) {
        int m = m0 + wm * 64 + i * 16 + g;
#pragma unroll
        for (int j = 0; j < 4; j++) {
            int nn = n0 + wn * 32 + j * 8 + 2 * tq;
            float2 bb = *(const float2*)(bias + nn);
            float* p = out + (size_t)m * DOUT + nn;
            *(float2*)p              = make_float2(acc[i][j][0] + bb.x, acc[i][j][1] + bb.y);
            *(float2*)(p + 8 * DOUT) = make_float2(acc[i][j][2] + bb.x, acc[i][j][3] + bb.y);
        }
    }
}

// ===========================================================================
// Attention: block = 64 queries of one (b,h); 128 threads = 4 warps.
// K/V bf16 hi/lo tiles via cp.async (double buffered). Q frags in registers.
// V fragments via ldmatrix.trans. 3-pass mma everywhere.
// ===========================================================================
#define APB      144                  // bytes per row (128 payload + 16 pad)
#define ATILE_B  (64 * APB)           // 9216
#define ASTAGE_B (4 * ATILE_B)        // 36864 (Khi,Klo,Vhi,Vlo)
#define ATTN_SMEM (2 * ASTAGE_B)      // 73728

__device__ __forceinline__ void aload_tile(const __nv_bfloat16* src, uint32_t dst, int t)
{
    int row = t >> 1, half = t & 1;
    const __nv_bfloat16* g = src + (size_t)row * HD_ + half * 32;
    uint32_t d = dst + row * APB + half * 64;
#pragma unroll
    for (int j = 0; j < 4; j++) CPA16(d + j * 16, g + j * 8);
}

__global__ __launch_bounds__(128, 3) void attn_k()
{
    extern __shared__ char sma[];
    uint32_t sb = scvta(sma);

    const int t    = threadIdx.x;
    const int lane = t & 31;
    const int w    = t >> 5;
    const int g    = lane >> 2;
    const int tq   = lane & 3;

    const int q0 = blockIdx.x * 64;
    const int h  = blockIdx.y;
    const int b  = blockIdx.z;
    const size_t hb = (size_t)(b * NH + h) * S_ * HD_;

    int kc0 = q0 - WIN; if (kc0 < 0) kc0 = 0;
    int kce = q0 + 64 + WIN; if (kce > S_) kce = S_;
    const int nch = (kce - kc0) >> 6;

    // prologue: chunk0 K/V -> stage0; Q -> stage1 (tiles 0,1)
    aload_tile(gk_h + hb + (size_t)kc0 * HD_, sb,               t);
    aload_tile(gk_l + hb + (size_t)kc0 * HD_, sb + ATILE_B,     t);
    aload_tile(gv_h + hb + (size_t)kc0 * HD_, sb + 2 * ATILE_B, t);
    aload_tile(gv_l + hb + (size_t)kc0 * HD_, sb + 3 * ATILE_B, t);
    CPC();
    aload_tile(gq_h + hb + (size_t)q0 * HD_, sb + ASTAGE_B,           t);
    aload_tile(gq_l + hb + (size_t)q0 * HD_, sb + ASTAGE_B + ATILE_B, t);
    CPC();
    CPW(0);
    __syncthreads();

    // Q fragments
    uint32_t qh[4][4], ql[4][4];
#pragma unroll
    for (int kc = 0; kc < 4; kc++) {
        int r = 16 * w + (lane & 15);
        uint32_t a = sb + ASTAGE_B + r * APB + kc * 32 + (lane >> 4) * 16;
        LDSM4(qh[kc][0], qh[kc][1], qh[kc][2], qh[kc][3], a);
        LDSM4(ql[kc][0], ql[kc][1], ql[kc][2], ql[kc][3], a + ATILE_B);
    }
    __syncthreads();   // all warps consumed Q before stage1 is overwritten

    float oacc[8][4];
#pragma unroll
    for (int j = 0; j < 8; j++)
#pragma unroll
        for (int c = 0; c < 4; c++) oacc[j][c] = 0.f;
    float m_[2] = {-INFINITY, -INFINITY};
    float l_[2] = {0.f, 0.f};
    const int row0 = q0 + 16 * w + g;

    for (int c = 0; c < nch; c++) {
        const int kc = kc0 + c * 64;
        if (c) { CPW(0); __syncthreads(); }
        if (c + 1 < nch) {
            uint32_t ns = sb + ((c + 1) & 1) * ASTAGE_B;
            size_t off = hb + (size_t)(kc + 64) * HD_;
            aload_tile(gk_h + off, ns,               t);
            aload_tile(gk_l + off, ns + ATILE_B,     t);
            aload_tile(gv_h + off, ns + 2 * ATILE_B, t);
            aload_tile(gv_l + off, ns + 3 * ATILE_B, t);
        }
        CPC();

        const uint32_t ks = sb + (c & 1) * ASTAGE_B;

        // ---- S = Q @ K^T (3-pass) ----
        float sacc[8][4];
#pragma unroll
        for (int j = 0; j < 8; j++)
#pragma unroll
            for (int cc = 0; cc < 4; cc++) sacc[j][cc] = 0.f;

#pragma unroll
        for (int kc2 = 0; kc2 < 4; kc2++) {
#pragma unroll
            for (int jp = 0; jp < 4; jp++) {
                int r = jp * 16 + (lane >> 4) * 8 + (lane & 7);
                uint32_t a = ks + r * APB + kc2 * 32 + ((lane >> 3) & 1) * 16;
                uint32_t bh0[2], bh1[2], bl0[2], bl1[2];
                LDSM4(bh0[0], bh0[1], bh1[0], bh1[1], a);
                LDSM4(bl0[0], bl0[1], bl1[0], bl1[1], a + ATILE_B);
                mma_bf16(sacc[2*jp],   qh[kc2], bh0);
                mma_bf16(sacc[2*jp],   ql[kc2], bh0);
                mma_bf16(sacc[2*jp],   qh[kc2], bl0);
                mma_bf16(sacc[2*jp+1], qh[kc2], bh1);
                mma_bf16(sacc[2*jp+1], ql[kc2], bh1);
                mma_bf16(sacc[2*jp+1], qh[kc2], bl1);
            }
        }

        // ---- mask + online softmax ----
#pragma unroll
        for (int half = 0; half < 2; half++) {
            int row = row0 + 8 * half;
            float mx = -INFINITY;
#pragma unroll
            for (int j = 0; j < 8; j++) {
                int col = kc + 8 * j + 2 * tq;
                float v0 = sacc[j][2 * half];
                float v1 = sacc[j][2 * half + 1];
                int d0 = row - col;     d0 = d0 < 0 ? -d0 : d0;
                int d1 = row - col - 1; d1 = d1 < 0 ? -d1 : d1;
                v0 = (d0 <= WIN) ? v0 * SCALE : -INFINITY;
                v1 = (d1 <= WIN) ? v1 * SCALE : -INFINITY;
                sacc[j][2 * half]     = v0;
                sacc[j][2 * half + 1] = v1;
                mx = fmaxf(mx, fmaxf(v0, v1));
            }
            mx = fmaxf(mx, __shfl_xor_sync(0xffffffffu, mx, 1, 4));
            mx = fmaxf(mx, __shfl_xor_sync(0xffffffffu, mx, 2, 4));

            float mn    = fmaxf(m_[half], mx);
            float msafe = (mn == -INFINITY) ? 0.f : mn;
            float alpha = __expf(m_[half] - msafe);
            m_[half] = mn;

            float rs = 0.f;
#pragma unroll
            for (int j = 0; j < 8; j++) {
                float p0 = __expf(sacc[j][2 * half]     - msafe);
                float p1 = __expf(sacc[j][2 * half + 1] - msafe);
                sacc[j][2 * half]     = p0;
                sacc[j][2 * half + 1] = p1;
                rs += p0 + p1;
            }
            rs += __shfl_xor_sync(0xffffffffu, rs, 1, 4);
            rs += __shfl_xor_sync(0xffffffffu, rs, 2, 4);
            l_[half] = l_[half] * alpha + rs;
#pragma unroll
            for (int j = 0; j < 8; j++) {
                oacc[j][2 * half]     *= alpha;
                oacc[j][2 * half + 1] *= alpha;
            }
        }

        // ---- O += P @ V (3-pass, V via ldmatrix.trans) ----
#pragma unroll
        for (int kp = 0; kp < 4; kp++) {
            uint32_t ph[4], pl[4];
            split2(sacc[2*kp][0],   sacc[2*kp][1],   ph[0], pl[0]);
            split2(sacc[2*kp][2],   sacc[2*kp][3],   ph[1], pl[1]);
            split2(sacc[2*kp+1][0], sacc[2*kp+1][1], ph[2], pl[2]);
            split2(sacc[2*kp+1][2], sacc[2*kp+1][3], ph[3], pl[3]);

#pragma unroll
            for (int jp = 0; jp < 4; jp++) {
                int keyrow = kp * 16 + ((lane >> 3) & 1) * 8 + (lane & 7);
                uint32_t a = ks + 2 * ATILE_B + keyrow * APB + (2 * jp + (lane >> 4)) * 16;
                uint32_t vh0[2], vh1[2], vl0[2], vl1[2];
                LDSM4T(vh0[0], vh0[1], vh1[0], vh1[1], a);
                LDSM4T(vl0[0], vl0[1], vl1[0], vl1[1], a + ATILE_B);
                mma_bf16(oacc[2*jp],   ph, vh0);
                mma_bf16(oacc[2*jp],   pl, vh0);
                mma_bf16(oacc[2*jp],   ph, vl0);
                mma_bf16(oacc[2*jp+1], ph, vh1);
                mma_bf16(oacc[2*jp+1], pl, vh1);
                mma_bf16(oacc[2*jp+1], ph, vl1);
            }
        }
    }

    // ---- finalize: O/l -> ctx bf16 hi/lo ----
    float rl0 = 1.f / l_[0];
    float rl1 = 1.f / l_[1];
    size_t c0 = ((size_t)b * S_ + row0) * DOUT + h * HD_;
    size_t c1 = c0 + 8 * DOUT;
#pragma unroll
    for (int j = 0; j < 8; j++) {
        int hd = 8 * j + 2 * tq;
        uint32_t hw, lw;
        split2(oacc[j][0] * rl0, oacc[j][1] * rl0, hw, lw);
        *(uint32_t*)(gc_h + c0 + hd) = hw;
        *(uint32_t*)(gc_l + c0 + hd) = lw;
        split2(oacc[j][2] * rl1, oacc[j][3] * rl1, hw, lw);
        *(uint32_t*)(gc_h + c1 + hd) = hw;
        *(uint32_t*)(gc_l + c1 + hd) = lw;
    }
}

// ===========================================================================
extern "C" void kernel_launch(void* const* d_in, const int* in_sizes, int n_in,
                              void* d_out, int out_size)
{
    const float* x    = (const float*)d_in[0];
    const float* wqkv = (const float*)d_in[1];
    const float* wout = (const float*)d_in[2];
    const float* bout = (const float*)d_in[3];
    float* out = (float*)d_out;

    __nv_bfloat16 *p_xh, *p_xl, *p_qh, *p_ql, *p_oh, *p_ol;
    cudaGetSymbolAddress((void**)&p_xh, gx_h);
    cudaGetSymbolAddress((void**)&p_xl, gx_l);
    cudaGetSymbolAddress((void**)&p_qh, gwq_h);
    cudaGetSymbolAddress((void**)&p_ql, gwq_l);
    cudaGetSymbolAddress((void**)&p_oh, gwo_h);
    cudaGetSymbolAddress((void**)&p_ol, gwo_l);

    cudaFuncSetAttribute(qkv_gemm_k, cudaFuncAttributeMaxDynamicSharedMemorySize, GEMM_SMEM);
    cudaFuncSetAttribute(out_gemm_k, cudaFuncAttributeMaxDynamicSharedMemorySize, GEMM_SMEM);
    cudaFuncSetAttribute(attn_k, cudaFuncAttributeMaxDynamicSharedMemorySize, ATTN_SMEM);

    split_kernel<<<NX / 4 / 256, 256>>>((const float4*)x, (uint2*)p_xh, (uint2*)p_xl, NX / 4);
    split_kernel<<<3 * DOUT * DIN / 4 / 256, 256>>>((const float4*)wqkv, (uint2*)p_qh,
                                                    (uint2*)p_ql, 3 * DOUT * DIN / 4);
    split_kernel<<<DOUT * DOUT / 4 / 256, 256>>>((const float4*)wout, (uint2*)p_oh,
                                                 (uint2*)p_ol, DOUT * DOUT / 4);

    qkv_gemm_k<<<dim3(3 * DOUT / 128, (B_ * S_) / 128), 256, GEMM_SMEM>>>();
    attn_k<<<dim3(S_ / 64, NH, B_), 128, ATTN_SMEM>>>();
    out_gemm_k<<<dim3(DOUT / 128, (B_ * S_) / 128), 256, GEMM_SMEM>>>(bout, out);
}

// round 6
// speedup vs baseline: 2.5875x; 1.1669x over previous
#include <cuda_runtime.h>
#include <cuda_bf16.h>
#include <math.h>
#include <stdint.h>

#define B_    2
#define S_    2048
#define DIN   1024
#define DOUT  1024
#define NH    16
#define HD_   64
#define WIN   256
#define SCALE 0.125f

#define NQKV (B_*NH*S_*HD_)
#define NX   (B_*S_*DIN)

__device__ __align__(16) __nv_bfloat16 gx_h[NX],  gx_l[NX];
__device__ __align__(16) __nv_bfloat16 gwq_h[3*DOUT*DIN], gwq_l[3*DOUT*DIN];
__device__ __align__(16) __nv_bfloat16 gwo_h[DOUT*DOUT],  gwo_l[DOUT*DOUT];
__device__ __align__(16) __nv_bfloat16 gq_h[NQKV], gq_l[NQKV];
__device__ __align__(16) __nv_bfloat16 gk_h[NQKV], gk_l[NQKV];
__device__ __align__(16) __nv_bfloat16 gv_h[NQKV], gv_l[NQKV];
__device__ __align__(16) __nv_bfloat16 gc_h[B_*S_*DOUT], gc_l[B_*S_*DOUT];

// ===========================================================================
__device__ __forceinline__ void split2(float x, float y, uint32_t& hi, uint32_t& lo) {
    __nv_bfloat16 hx = __float2bfloat16(x);
    __nv_bfloat16 hy = __float2bfloat16(y);
    float rx = x - __bfloat162float(hx);
    float ry = y - __bfloat162float(hy);
    __nv_bfloat16 lx = __float2bfloat16(rx);
    __nv_bfloat16 ly = __float2bfloat16(ry);
    __nv_bfloat162 hv; hv.x = hx; hv.y = hy;
    __nv_bfloat162 lv; lv.x = lx; lv.y = ly;
    hi = *(uint32_t*)&hv;
    lo = *(uint32_t*)&lv;
}

__device__ __forceinline__ void mma_bf16(float c[4], const uint32_t a[4], const uint32_t b[2]) {
    asm volatile(
        "mma.sync.aligned.m16n8k16.row.col.f32.bf16.bf16.f32 "
        "{%0,%1,%2,%3}, {%4,%5,%6,%7}, {%8,%9}, {%0,%1,%2,%3};"
        : "+f"(c[0]), "+f"(c[1]), "+f"(c[2]), "+f"(c[3])
        : "r"(a[0]), "r"(a[1]), "r"(a[2]), "r"(a[3]), "r"(b[0]), "r"(b[1]));
}

#define CPA16(dst, src) asm volatile("cp.async.cg.shared.global [%0], [%1], 16;" :: "r"(dst), "l"(src))
#define CPC()  asm volatile("cp.async.commit_group;" ::: "memory")
#define CPW(n) asm volatile("cp.async.wait_group %0;" :: "n"(n) : "memory")

#define LDSM4(d0,d1,d2,d3,a) \
    asm volatile("ldmatrix.sync.aligned.m8n8.x4.shared.b16 {%0,%1,%2,%3}, [%4];" \
                 : "=r"(d0),"=r"(d1),"=r"(d2),"=r"(d3) : "r"(a))
#define LDSM4T(d0,d1,d2,d3,a) \
    asm volatile("ldmatrix.sync.aligned.m8n8.x4.trans.shared.b16 {%0,%1,%2,%3}, [%4];" \
                 : "=r"(d0),"=r"(d1),"=r"(d2),"=r"(d3) : "r"(a))

__device__ __forceinline__ uint32_t scvta(const void* p) {
    return (uint32_t)__cvta_generic_to_shared(p);
}

// ===========================================================================
__global__ void split_kernel(const float4* __restrict__ src, uint2* __restrict__ hi,
                             uint2* __restrict__ lo, int n4)
{
    int i = blockIdx.x * 256 + threadIdx.x;
    if (i < n4) {
        float4 v = src[i];
        uint32_t h0, l0, h1, l1;
        split2(v.x, v.y, h0, l0);
        split2(v.z, v.w, h1, l1);
        hi[i] = make_uint2(h0, h1);
        lo[i] = make_uint2(l0, l1);
    }
}

// ===========================================================================
// GEMM: C[128x256] per CTA = A[128xK] @ B[256xK]^T, K=1024, bf16 3-pass.
// 256 threads = 8 warps (2M x 4N), warp tile 64x64, BK=32, 3-stage cp.async.
// Stage: Ahi(128x80B) Alo Bhi(256x80B) Blo = 61440 B.
// ===========================================================================
#define PRB       80
#define GA_B      (128 * PRB)          // 10240
#define GB_B      (256 * PRB)          // 20480
#define GSTAGE_B  (2 * GA_B + 2 * GB_B)  // 61440
#define GOFF_AL   GA_B
#define GOFF_BH   (2 * GA_B)
#define GOFF_BL   (2 * GA_B + GB_B)
#define GEMM_SMEM (3 * GSTAGE_B)       // 184320

__device__ __forceinline__ void gstage(const __nv_bfloat16* Ah, const __nv_bfloat16* Al,
                                       const __nv_bfloat16* Bh, const __nv_bfloat16* Bl,
                                       int k0, uint32_t sb, int t)
{
#pragma unroll
    for (int i = 0; i < 2; i++) {            // A: 512 cp over 2 iters
        int idx = t + i * 256;
        int row = idx >> 2, c = idx & 3;
        uint32_t d = sb + row * PRB + c * 16;
        CPA16(d,          Ah + (size_t)row * 1024 + k0 + c * 8);
        CPA16(d + GOFF_AL, Al + (size_t)row * 1024 + k0 + c * 8);
    }
#pragma unroll
    for (int i = 0; i < 4; i++) {            // B: 1024 cp over 4 iters
        int idx = t + i * 256;
        int row = idx >> 2, c = idx & 3;
        uint32_t d = sb + GOFF_BH + row * PRB + c * 16;
        CPA16(d,               Bh + (size_t)row * 1024 + k0 + c * 8);
        CPA16(d + GB_B,        Bl + (size_t)row * 1024 + k0 + c * 8);
    }
}

__device__ __forceinline__ void gcompute(uint32_t sb, int lane, int wm, int wn,
                                         float acc[4][8][4])
{
#pragma unroll
    for (int kc = 0; kc < 2; kc++) {
        uint32_t ah[4][4], al[4][4], bh[8][2], bl[8][2];
#pragma unroll
        for (int i = 0; i < 4; i++) {
            int r = wm * 64 + i * 16 + (lane & 15);
            uint32_t a = sb + r * PRB + kc * 32 + (lane >> 4) * 16;
            LDSM4(ah[i][0], ah[i][1], ah[i][2], ah[i][3], a);
            LDSM4(al[i][0], al[i][1], al[i][2], al[i][3], a + GOFF_AL);
        }
#pragma unroll
        for (int jp = 0; jp < 4; jp++) {
            int r = wn * 64 + jp * 16 + (lane >> 4) * 8 + (lane & 7);
            uint32_t a = sb + GOFF_BH + r * PRB + kc * 32 + ((lane >> 3) & 1) * 16;
            LDSM4(bh[2*jp][0], bh[2*jp][1], bh[2*jp+1][0], bh[2*jp+1][1], a);
            LDSM4(bl[2*jp][0], bl[2*jp][1], bl[2*jp+1][0], bl[2*jp+1][1], a + GB_B);
        }
#pragma unroll
        for (int i = 0; i < 4; i++)
#pragma unroll
            for (int j = 0; j < 8; j++) mma_bf16(acc[i][j], ah[i], bh[j]);
#pragma unroll
        for (int i = 0; i < 4; i++)
#pragma unroll
            for (int j = 0; j < 8; j++) mma_bf16(acc[i][j], al[i], bh[j]);
#pragma unroll
        for (int i = 0; i < 4; i++)
#pragma unroll
            for (int j = 0; j < 8; j++) mma_bf16(acc[i][j], ah[i], bl[j]);
    }
}

__device__ __forceinline__ void gemm_main(const __nv_bfloat16* Ah, const __nv_bfloat16* Al,
                                          const __nv_bfloat16* Bh, const __nv_bfloat16* Bl,
                                          uint32_t sb, float acc[4][8][4])
{
    const int t = threadIdx.x;
    const int lane = t & 31, wid = t >> 5;
    const int wm = wid >> 2, wn = wid & 3;

#pragma unroll
    for (int i = 0; i < 4; i++)
#pragma unroll
        for (int j = 0; j < 8; j++)
#pragma unroll
            for (int c = 0; c < 4; c++) acc[i][j][c] = 0.f;

    gstage(Ah, Al, Bh, Bl, 0,  sb, t);             CPC();
    gstage(Ah, Al, Bh, Bl, 32, sb + GSTAGE_B, t);  CPC();

    for (int ks = 0; ks < 32; ks++) {
        CPW(1);
        __syncthreads();
        if (ks < 30)
            gstage(Ah, Al, Bh, Bl, (ks + 2) * 32, sb + ((ks + 2) % 3) * GSTAGE_B, t);
        CPC();
        gcompute(sb + (ks % 3) * GSTAGE_B, lane, wm, wn, acc);
    }
}

__global__ __launch_bounds__(256, 1) void qkv_gemm_k()
{
    extern __shared__ char smg[];
    uint32_t sb = scvta(smg);
    const int m0 = blockIdx.y * 128;
    const int n0 = blockIdx.x * 256;

    float acc[4][8][4];
    gemm_main(gx_h + (size_t)m0 * 1024, gx_l + (size_t)m0 * 1024,
              gwq_h + (size_t)n0 * 1024, gwq_l + (size_t)n0 * 1024, sb, acc);

    const int t = threadIdx.x;
    const int lane = t & 31, wid = t >> 5;
    const int wm = wid >> 2, wn = wid & 3;
    const int g = lane >> 2, tq = lane & 3;

    // n0 is a multiple of 256; 1024-boundaries are multiples of 256.
    const int which = n0 >> 10;
    __nv_bfloat16* dh = (which == 0) ? gq_h : (which == 1) ? gk_h : gv_h;
    __nv_bfloat16* dl = (which == 0) ? gq_l : (which == 1) ? gk_l : gv_l;
    const int h = ((n0 + wn * 64) >> 6) & (NH - 1);

#pragma unroll
    for (int i = 0; i < 4; i++) {
        int m = m0 + wm * 64 + i * 16 + g;
        int b = m >> 11, s = m & (S_ - 1);
#pragma unroll
        for (int j = 0; j < 8; j++) {
            int hd = j * 8 + 2 * tq;
            size_t idx = (((size_t)(b * NH + h) * S_ + s) * HD_ + hd);
            uint32_t hw, lw;
            split2(acc[i][j][0], acc[i][j][1], hw, lw);
            *(uint32_t*)(dh + idx) = hw;
            *(uint32_t*)(dl + idx) = lw;
            split2(acc[i][j][2], acc[i][j][3], hw, lw);
            *(uint32_t*)(dh + idx + 8 * HD_) = hw;
            *(uint32_t*)(dl + idx + 8 * HD_) = lw;
        }
    }
}

__global__ __launch_bounds__(256, 1) void out_gemm_k(const float* __restrict__ bias,
                                                     float* __restrict__ out)
{
    extern __shared__ char smg[];
    uint32_t sb = scvta(smg);
    const int m0 = blockIdx.y * 128;
    const int n0 = blockIdx.x * 256;

    float acc[4][8][4];
    gemm_main(gc_h + (size_t)m0 * 1024, gc_l + (size_t)m0 * 1024,
              gwo_h + (size_t)n0 * 1024, gwo_l + (size_t)n0 * 1024, sb, acc);

    const int t = threadIdx.x;
    const int lane = t & 31, wid = t >> 5;
    const int wm = wid >> 2, wn = wid & 3;
    const int g = lane >> 2, tq = lane & 3;

#pragma unroll
    for (int i = 0; i < 4; i++) {
        int m = m0 + wm * 64 + i * 16 + g;
#pragma unroll
        for (int j = 0; j < 8; j++) {
            int nn = n0 + wn * 64 + j * 8 + 2 * tq;
            float2 bb = *(const float2*)(bias + nn);
            float* p = out + (size_t)m * DOUT + nn;
            *(float2*)p              = make_float2(acc[i][j][0] + bb.x, acc[i][j][1] + bb.y);
            *(float2*)(p + 8 * DOUT) = make_float2(acc[i][j][2] + bb.x, acc[i][j][3] + bb.y);
        }
    }
}

// ===========================================================================
// Attention: block = 128 queries of one (b,h); 256 threads = 8 warps.
// Warp w owns rows 16w..16w+15. Halo amortized: 10 chunks per 128 queries.
// ===========================================================================
#define APB      144
#define ATILE_B  (64 * APB)            // 9216
#define ASTAGE_B (4 * ATILE_B)         // 36864
#define ATTN_SMEM (2 * ASTAGE_B)       // 73728

// 64-row x 64-col bf16 tile load (512 cp over 256 threads -> 2/thread)
__device__ __forceinline__ void aload_tile(const __nv_bfloat16* src, uint32_t dst, int t)
{
#pragma unroll
    for (int i = 0; i < 2; i++) {
        int idx = t + i * 256;
        int row = idx >> 3, c = idx & 7;
        CPA16(dst + row * APB + c * 16, src + (size_t)row * HD_ + c * 8);
    }
}
// 128-row Q tile (1024 cp -> 4/thread)
__device__ __forceinline__ void aload_q(const __nv_bfloat16* src, uint32_t dst, int t)
{
#pragma unroll
    for (int i = 0; i < 4; i++) {
        int idx = t + i * 256;
        int row = idx >> 3, c = idx & 7;
        CPA16(dst + row * APB + c * 16, src + (size_t)row * HD_ + c * 8);
    }
}

__global__ __launch_bounds__(256, 1) void attn_k()
{
    extern __shared__ char sma[];
    uint32_t sb = scvta(sma);

    const int t    = threadIdx.x;
    const int lane = t & 31;
    const int w    = t >> 5;
    const int g    = lane >> 2;
    const int tq   = lane & 3;

    const int q0 = blockIdx.x * 128;
    const int h  = blockIdx.y;
    const int b  = blockIdx.z;
    const size_t hb = (size_t)(b * NH + h) * S_ * HD_;

    int kc0 = q0 - WIN; if (kc0 < 0) kc0 = 0;
    int kce = q0 + 128 + WIN; if (kce > S_) kce = S_;
    const int nch = (kce - kc0) >> 6;

    // chunk0 K/V -> stage0; Q -> stage1 (Qhi rows 0..127, then Qlo)
    aload_tile(gk_h + hb + (size_t)kc0 * HD_, sb,               t);
    aload_tile(gk_l + hb + (size_t)kc0 * HD_, sb + ATILE_B,     t);
    aload_tile(gv_h + hb + (size_t)kc0 * HD_, sb + 2 * ATILE_B, t);
    aload_tile(gv_l + hb + (size_t)kc0 * HD_, sb + 3 * ATILE_B, t);
    CPC();
    aload_q(gq_h + hb + (size_t)q0 * HD_, sb + ASTAGE_B,               t);
    aload_q(gq_l + hb + (size_t)q0 * HD_, sb + ASTAGE_B + 2 * ATILE_B, t);
    CPC();
    CPW(0);
    __syncthreads();

    uint32_t qh[4][4], ql[4][4];
#pragma unroll
    for (int kc = 0; kc < 4; kc++) {
        int r = 16 * w + (lane & 15);
        uint32_t a = sb + ASTAGE_B + r * APB + kc * 32 + (lane >> 4) * 16;
        LDSM4(qh[kc][0], qh[kc][1], qh[kc][2], qh[kc][3], a);
        LDSM4(ql[kc][0], ql[kc][1], ql[kc][2], ql[kc][3], a + 2 * ATILE_B);
    }
    __syncthreads();

    float oacc[8][4];
#pragma unroll
    for (int j = 0; j < 8; j++)
#pragma unroll
        for (int c = 0; c < 4; c++) oacc[j][c] = 0.f;
    float m_[2] = {-INFINITY, -INFINITY};
    float l_[2] = {0.f, 0.f};
    const int row0 = q0 + 16 * w + g;

    for (int c = 0; c < nch; c++) {
        const int kc = kc0 + c * 64;
        if (c) { CPW(0); __syncthreads(); }
        if (c + 1 < nch) {
            uint32_t ns = sb + ((c + 1) & 1) * ASTAGE_B;
            size_t off = hb + (size_t)(kc + 64) * HD_;
            aload_tile(gk_h + off, ns,               t);
            aload_tile(gk_l + off, ns + ATILE_B,     t);
            aload_tile(gv_h + off, ns + 2 * ATILE_B, t);
            aload_tile(gv_l + off, ns + 3 * ATILE_B, t);
        }
        CPC();

        const uint32_t ks = sb + (c & 1) * ASTAGE_B;

        // ---- S = Q @ K^T (3-pass) ----
        float sacc[8][4];
#pragma unroll
        for (int j = 0; j < 8; j++)
#pragma unroll
            for (int cc = 0; cc < 4; cc++) sacc[j][cc] = 0.f;

#pragma unroll
        for (int kc2 = 0; kc2 < 4; kc2++) {
#pragma unroll
            for (int jp = 0; jp < 4; jp++) {
                int r = jp * 16 + (lane >> 4) * 8 + (lane & 7);
                uint32_t a = ks + r * APB + kc2 * 32 + ((lane >> 3) & 1) * 16;
                uint32_t bh0[2], bh1[2], bl0[2], bl1[2];
                LDSM4(bh0[0], bh0[1], bh1[0], bh1[1], a);
                LDSM4(bl0[0], bl0[1], bl1[0], bl1[1], a + ATILE_B);
                mma_bf16(sacc[2*jp],   qh[kc2], bh0);
                mma_bf16(sacc[2*jp],   ql[kc2], bh0);
                mma_bf16(sacc[2*jp],   qh[kc2], bl0);
                mma_bf16(sacc[2*jp+1], qh[kc2], bh1);
                mma_bf16(sacc[2*jp+1], ql[kc2], bh1);
                mma_bf16(sacc[2*jp+1], qh[kc2], bl1);
            }
        }

        // ---- mask + online softmax ----
#pragma unroll
        for (int half = 0; half < 2; half++) {
            int row = row0 + 8 * half;
            float mx = -INFINITY;
#pragma unroll
            for (int j = 0; j < 8; j++) {
                int col = kc + 8 * j + 2 * tq;
                float v0 = sacc[j][2 * half];
                float v1 = sacc[j][2 * half + 1];
                int d0 = row - col;     d0 = d0 < 0 ? -d0 : d0;
                int d1 = row - col - 1; d1 = d1 < 0 ? -d1 : d1;
                v0 = (d0 <= WIN) ? v0 * SCALE : -INFINITY;
                v1 = (d1 <= WIN) ? v1 * SCALE : -INFINITY;
                sacc[j][2 * half]     = v0;
                sacc[j][2 * half + 1] = v1;
                mx = fmaxf(mx, fmaxf(v0, v1));
            }
            mx = fmaxf(mx, __shfl_xor_sync(0xffffffffu, mx, 1, 4));
            mx = fmaxf(mx, __shfl_xor_sync(0xffffffffu, mx, 2, 4));

            float mn    = fmaxf(m_[half], mx);
            float msafe = (mn == -INFINITY) ? 0.f : mn;
            float alpha = __expf(m_[half] - msafe);
            m_[half] = mn;

            float rs = 0.f;
#pragma unroll
            for (int j = 0; j < 8; j++) {
                float p0 = __expf(sacc[j][2 * half]     - msafe);
                float p1 = __expf(sacc[j][2 * half + 1] - msafe);
                sacc[j][2 * half]     = p0;
                sacc[j][2 * half + 1] = p1;
                rs += p0 + p1;
            }
            rs += __shfl_xor_sync(0xffffffffu, rs, 1, 4);
            rs += __shfl_xor_sync(0xffffffffu, rs, 2, 4);
            l_[half] = l_[half] * alpha + rs;
#pragma unroll
            for (int j = 0; j < 8; j++) {
                oacc[j][2 * half]     *= alpha;
                oacc[j][2 * half + 1] *= alpha;
            }
        }

        // ---- O += P @ V (3-pass, V via ldmatrix.trans) ----
#pragma unroll
        for (int kp = 0; kp < 4; kp++) {
            uint32_t ph[4], pl[4];
            split2(sacc[2*kp][0],   sacc[2*kp][1],   ph[0], pl[0]);
            split2(sacc[2*kp][2],   sacc[2*kp][3],   ph[1], pl[1]);
            split2(sacc[2*kp+1][0], sacc[2*kp+1][1], ph[2], pl[2]);
            split2(sacc[2*kp+1][2], sacc[2*kp+1][3], ph[3], pl[3]);

#pragma unroll
            for (int jp = 0; jp < 4; jp++) {
                int keyrow = kp * 16 + ((lane >> 3) & 1) * 8 + (lane & 7);
                uint32_t a = ks + 2 * ATILE_B + keyrow * APB + (2 * jp + (lane >> 4)) * 16;
                uint32_t vh0[2], vh1[2], vl0[2], vl1[2];
                LDSM4T(vh0[0], vh0[1], vh1[0], vh1[1], a);
                LDSM4T(vl0[0], vl0[1], vl1[0], vl1[1], a + ATILE_B);
                mma_bf16(oacc[2*jp],   ph, vh0);
                mma_bf16(oacc[2*jp],   pl, vh0);
                mma_bf16(oacc[2*jp],   ph, vl0);
                mma_bf16(oacc[2*jp+1], ph, vh1);
                mma_bf16(oacc[2*jp+1], pl, vh1);
                mma_bf16(oacc[2*jp+1], ph, vl1);
            }
        }
    }

    // ---- finalize ----
    float rl0 = 1.f / l_[0];
    float rl1 = 1.f / l_[1];
    size_t c0 = ((size_t)b * S_ + row0) * DOUT + h * HD_;
    size_t c1 = c0 + 8 * DOUT;
#pragma unroll
    for (int j = 0; j < 8; j++) {
        int hd = 8 * j + 2 * tq;
        uint32_t hw, lw;
        split2(oacc[j][0] * rl0, oacc[j][1] * rl0, hw, lw);
        *(uint32_t*)(gc_h + c0 + hd) = hw;
        *(uint32_t*)(gc_l + c0 + hd) = lw;
        split2(oacc[j][2] * rl1, oacc[j][3] * rl1, hw, lw);
        *(uint32_t*)(gc_h + c1 + hd) = hw;
        *(uint32_t*)(gc_l + c1 + hd) = lw;
    }
}

// ===========================================================================
extern "C" void kernel_launch(void* const* d_in, const int* in_sizes, int n_in,
                              void* d_out, int out_size)
{
    const float* x    = (const float*)d_in[0];
    const float* wqkv = (const float*)d_in[1];
    const float* wout = (const float*)d_in[2];
    const float* bout = (const float*)d_in[3];
    float* out = (float*)d_out;

    __nv_bfloat16 *p_xh, *p_xl, *p_qh, *p_ql, *p_oh, *p_ol;
    cudaGetSymbolAddress((void**)&p_xh, gx_h);
    cudaGetSymbolAddress((void**)&p_xl, gx_l);
    cudaGetSymbolAddress((void**)&p_qh, gwq_h);
    cudaGetSymbolAddress((void**)&p_ql, gwq_l);
    cudaGetSymbolAddress((void**)&p_oh, gwo_h);
    cudaGetSymbolAddress((void**)&p_ol, gwo_l);

    cudaFuncSetAttribute(qkv_gemm_k, cudaFuncAttributeMaxDynamicSharedMemorySize, GEMM_SMEM);
    cudaFuncSetAttribute(out_gemm_k, cudaFuncAttributeMaxDynamicSharedMemorySize, GEMM_SMEM);
    cudaFuncSetAttribute(attn_k, cudaFuncAttributeMaxDynamicSharedMemorySize, ATTN_SMEM);

    split_kernel<<<NX / 4 / 256, 256>>>((const float4*)x, (uint2*)p_xh, (uint2*)p_xl, NX / 4);
    split_kernel<<<3 * DOUT * DIN / 4 / 256, 256>>>((const float4*)wqkv, (uint2*)p_qh,
                                                    (uint2*)p_ql, 3 * DOUT * DIN / 4);
    split_kernel<<<DOUT * DOUT / 4 / 256, 256>>>((const float4*)wout, (uint2*)p_oh,
                                                 (uint2*)p_ol, DOUT * DOUT / 4);

    qkv_gemm_k<<<dim3(3 * DOUT / 256, (B_ * S_) / 128), 256, GEMM_SMEM>>>();
    attn_k<<<dim3(S_ / 128, NH, B_), 256, ATTN_SMEM>>>();
    out_gemm_k<<<dim3(DOUT / 256, (B_ * S_) / 128), 256, GEMM_SMEM>>>(bout, out);
}

// round 7
// speedup vs baseline: 3.0847x; 1.1921x over previous
#include <cuda_runtime.h>
#include <cuda_bf16.h>
#include <math.h>
#include <stdint.h>

#define B_    2
#define S_    2048
#define DIN   1024
#define DOUT  1024
#define NH    16
#define HD_   64
#define WIN   256
#define SCALE 0.125f

#define NQKV (B_*NH*S_*HD_)
#define NX   (B_*S_*DIN)

__device__ __align__(16) __nv_bfloat16 gx_h[NX],  gx_l[NX];
__device__ __align__(16) __nv_bfloat16 gwq_h[3*DOUT*DIN], gwq_l[3*DOUT*DIN];
__device__ __align__(16) __nv_bfloat16 gwo_h[DOUT*DOUT],  gwo_l[DOUT*DOUT];
__device__ __align__(16) __nv_bfloat16 gq_h[NQKV], gq_l[NQKV];
__device__ __align__(16) __nv_bfloat16 gk_h[NQKV], gk_l[NQKV];
__device__ __align__(16) __nv_bfloat16 gv_h[NQKV], gv_l[NQKV];
__device__ __align__(16) __nv_bfloat16 gc_h[B_*S_*DOUT], gc_l[B_*S_*DOUT];

// ===========================================================================
__device__ __forceinline__ void split2(float x, float y, uint32_t& hi, uint32_t& lo) {
    __nv_bfloat16 hx = __float2bfloat16(x);
    __nv_bfloat16 hy = __float2bfloat16(y);
    float rx = x - __bfloat162float(hx);
    float ry = y - __bfloat162float(hy);
    __nv_bfloat16 lx = __float2bfloat16(rx);
    __nv_bfloat16 ly = __float2bfloat16(ry);
    __nv_bfloat162 hv; hv.x = hx; hv.y = hy;
    __nv_bfloat162 lv; lv.x = lx; lv.y = ly;
    hi = *(uint32_t*)&hv;
    lo = *(uint32_t*)&lv;
}

__device__ __forceinline__ void mma_bf16(float c[4], const uint32_t a[4], const uint32_t b[2]) {
    asm volatile(
        "mma.sync.aligned.m16n8k16.row.col.f32.bf16.bf16.f32 "
        "{%0,%1,%2,%3}, {%4,%5,%6,%7}, {%8,%9}, {%0,%1,%2,%3};"
        : "+f"(c[0]), "+f"(c[1]), "+f"(c[2]), "+f"(c[3])
        : "r"(a[0]), "r"(a[1]), "r"(a[2]), "r"(a[3]), "r"(b[0]), "r"(b[1]));
}

#define CPA16(dst, src) asm volatile("cp.async.cg.shared.global [%0], [%1], 16;" :: "r"(dst), "l"(src))
#define CPC()  asm volatile("cp.async.commit_group;" ::: "memory")
#define CPW(n) asm volatile("cp.async.wait_group %0;" :: "n"(n) : "memory")

#define LDSM4(d0,d1,d2,d3,a) \
    asm volatile("ldmatrix.sync.aligned.m8n8.x4.shared.b16 {%0,%1,%2,%3}, [%4];" \
                 : "=r"(d0),"=r"(d1),"=r"(d2),"=r"(d3) : "r"(a))
#define LDSM4T(d0,d1,d2,d3,a) \
    asm volatile("ldmatrix.sync.aligned.m8n8.x4.trans.shared.b16 {%0,%1,%2,%3}, [%4];" \
                 : "=r"(d0),"=r"(d1),"=r"(d2),"=r"(d3) : "r"(a))

__device__ __forceinline__ uint32_t scvta(const void* p) {
    return (uint32_t)__cvta_generic_to_shared(p);
}

// ===========================================================================
__global__ void split_kernel(const float4* __restrict__ src, uint2* __restrict__ hi,
                             uint2* __restrict__ lo, int n4)
{
    int i = blockIdx.x * 256 + threadIdx.x;
    if (i < n4) {
        float4 v = src[i];
        uint32_t h0, l0, h1, l1;
        split2(v.x, v.y, h0, l0);
        split2(v.z, v.w, h1, l1);
        hi[i] = make_uint2(h0, h1);
        lo[i] = make_uint2(l0, l1);
    }
}

// ===========================================================================
// GEMM: C[128x256] per CTA, 8 warps (2M x 4N), warp tile 64x64, BK=32,
// 3-stage cp.async, bf16 3-pass. cp.async + lo-LDSM interleaved among MMAs.
// ===========================================================================
#define PRB       80
#define GA_B      (128 * PRB)
#define GB_B      (256 * PRB)
#define GSTAGE_B  (2 * GA_B + 2 * GB_B)
#define GOFF_AL   GA_B
#define GOFF_BH   (2 * GA_B)
#define GOFF_BL   (GOFF_BH + GB_B)
#define GEMM_SMEM (3 * GSTAGE_B)

// full-stage staging (prologue only)
__device__ __forceinline__ void gstage(const __nv_bfloat16* Ah, const __nv_bfloat16* Al,
                                       const __nv_bfloat16* Bh, const __nv_bfloat16* Bl,
                                       int k0, uint32_t sb, int t)
{
#pragma unroll
    for (int i = 0; i < 2; i++) {
        int idx = t + i * 256;
        int row = idx >> 2, c = idx & 3;
        uint32_t d = sb + row * PRB + c * 16;
        CPA16(d,           Ah + (size_t)row * 1024 + k0 + c * 8);
        CPA16(d + GOFF_AL, Al + (size_t)row * 1024 + k0 + c * 8);
    }
#pragma unroll
    for (int i = 0; i < 4; i++) {
        int idx = t + i * 256;
        int row = idx >> 2, c = idx & 3;
        uint32_t d = sb + GOFF_BH + row * PRB + c * 16;
        CPA16(d,        Bh + (size_t)row * 1024 + k0 + c * 8);
        CPA16(d + GB_B, Bl + (size_t)row * 1024 + k0 + c * 8);
    }
}

// one of the 12 per-thread cp.async ops for a stage, issued between MMA groups
__device__ __forceinline__ void docp(int j,
                                     const __nv_bfloat16* Ah, const __nv_bfloat16* Al,
                                     const __nv_bfloat16* Bh, const __nv_bfloat16* Bl,
                                     int k0, uint32_t sb, int t)
{
    if (j < 4) {
        int it = j >> 1;
        int idx = t + it * 256;
        int row = idx >> 2, c = idx & 3;
        uint32_t d = sb + row * PRB + c * 16;
        if (j & 1) CPA16(d + GOFF_AL, Al + (size_t)row * 1024 + k0 + c * 8);
        else       CPA16(d,           Ah + (size_t)row * 1024 + k0 + c * 8);
    } else {
        int jj = j - 4;
        int it = jj >> 1;
        int idx = t + it * 256;
        int row = idx >> 2, c = idx & 3;
        uint32_t d = sb + GOFF_BH + row * PRB + c * 16;
        if (jj & 1) CPA16(d + GB_B, Bl + (size_t)row * 1024 + k0 + c * 8);
        else        CPA16(d,        Bh + (size_t)row * 1024 + k0 + c * 8);
    }
}

__device__ __forceinline__ void mma_g8(float (*accr)[4], const uint32_t a[4],
                                       const uint32_t (*b)[2])
{
#pragma unroll
    for (int j = 0; j < 8; j++) mma_bf16(accr[j], a, b[j]);
}

__device__ __forceinline__ void gemm_main(const __nv_bfloat16* Ah, const __nv_bfloat16* Al,
                                          const __nv_bfloat16* Bh, const __nv_bfloat16* Bl,
                                          uint32_t sb, float acc[4][8][4])
{
    const int t = threadIdx.x;
    const int lane = t & 31, wid = t >> 5;
    const int wm = wid >> 2, wn = wid & 3;

#pragma unroll
    for (int i = 0; i < 4; i++)
#pragma unroll
        for (int j = 0; j < 8; j++)
#pragma unroll
            for (int c = 0; c < 4; c++) acc[i][j][c] = 0.f;

    gstage(Ah, Al, Bh, Bl, 0,  sb, t);             CPC();
    gstage(Ah, Al, Bh, Bl, 32, sb + GSTAGE_B, t);  CPC();

    for (int ks = 0; ks < 32; ks++) {
        CPW(1);
        __syncthreads();
        const uint32_t cs = sb + (ks % 3) * GSTAGE_B;
        const uint32_t ps = sb + ((ks + 2) % 3) * GSTAGE_B;
        const int k0n = (ks + 2) * 32;
        const bool pf = (ks < 30);

#pragma unroll
        for (int kc = 0; kc < 2; kc++) {
            uint32_t ah[4][4], al[4][4], bh[8][2], bl[8][2];
            // B-hi and A-hi fragments (minimal prefix)
#pragma unroll
            for (int jp = 0; jp < 4; jp++) {
                int r = wn * 64 + jp * 16 + (lane >> 4) * 8 + (lane & 7);
                uint32_t a = cs + GOFF_BH + r * PRB + kc * 32 + ((lane >> 3) & 1) * 16;
                LDSM4(bh[2*jp][0], bh[2*jp][1], bh[2*jp+1][0], bh[2*jp+1][1], a);
            }
#pragma unroll
            for (int i = 0; i < 4; i++) {
                int r = wm * 64 + i * 16 + (lane & 15);
                LDSM4(ah[i][0], ah[i][1], ah[i][2], ah[i][3],
                      cs + r * PRB + kc * 32 + (lane >> 4) * 16);
            }
            // pass 1: Ah*Bh, with A-lo LDSM + cp interleaved
#pragma unroll
            for (int i = 0; i < 4; i++) {
                mma_g8(acc[i], ah[i], bh);
                int r = wm * 64 + i * 16 + (lane & 15);
                LDSM4(al[i][0], al[i][1], al[i][2], al[i][3],
                      cs + GOFF_AL + r * PRB + kc * 32 + (lane >> 4) * 16);
                if (pf && kc == 0) docp(i, Ah, Al, Bh, Bl, k0n, ps, t);
            }
            // pass 2: Al*Bh, with B-lo LDSM + cp interleaved
#pragma unroll
            for (int i = 0; i < 4; i++) {
                mma_g8(acc[i], al[i], bh);
                int r = wn * 64 + i * 16 + (lane >> 4) * 8 + (lane & 7);
                uint32_t a = cs + GOFF_BL + r * PRB + kc * 32 + ((lane >> 3) & 1) * 16;
                LDSM4(bl[2*i][0], bl[2*i][1], bl[2*i+1][0], bl[2*i+1][1], a);
                if (pf && kc == 0) docp(4 + i, Ah, Al, Bh, Bl, k0n, ps, t);
            }
            // pass 3: Ah*Bl, with cp interleaved
#pragma unroll
            for (int i = 0; i < 4; i++) {
                mma_g8(acc[i], ah[i], bl);
                if (pf && kc == 0) docp(8 + i, Ah, Al, Bh, Bl, k0n, ps, t);
            }
        }
        CPC();
    }
}

__global__ __launch_bounds__(256, 1) void qkv_gemm_k()
{
    extern __shared__ char smg[];
    uint32_t sb = scvta(smg);
    const int m0 = blockIdx.y * 128;
    const int n0 = blockIdx.x * 256;

    float acc[4][8][4];
    gemm_main(gx_h + (size_t)m0 * 1024, gx_l + (size_t)m0 * 1024,
              gwq_h + (size_t)n0 * 1024, gwq_l + (size_t)n0 * 1024, sb, acc);

    const int t = threadIdx.x;
    const int lane = t & 31, wid = t >> 5;
    const int wm = wid >> 2, wn = wid & 3;
    const int g = lane >> 2, tq = lane & 3;

    const int which = n0 >> 10;
    __nv_bfloat16* dh = (which == 0) ? gq_h : (which == 1) ? gk_h : gv_h;
    __nv_bfloat16* dl = (which == 0) ? gq_l : (which == 1) ? gk_l : gv_l;
    const int h = ((n0 + wn * 64) >> 6) & (NH - 1);

#pragma unroll
    for (int i = 0; i < 4; i++) {
        int m = m0 + wm * 64 + i * 16 + g;
        int b = m >> 11, s = m & (S_ - 1);
#pragma unroll
        for (int j = 0; j < 8; j++) {
            int hd = j * 8 + 2 * tq;
            size_t idx = (((size_t)(b * NH + h) * S_ + s) * HD_ + hd);
            uint32_t hw, lw;
            split2(acc[i][j][0], acc[i][j][1], hw, lw);
            *(uint32_t*)(dh + idx) = hw;
            *(uint32_t*)(dl + idx) = lw;
            split2(acc[i][j][2], acc[i][j][3], hw, lw);
            *(uint32_t*)(dh + idx + 8 * HD_) = hw;
            *(uint32_t*)(dl + idx + 8 * HD_) = lw;
        }
    }
}

__global__ __launch_bounds__(256, 1) void out_gemm_k(const float* __restrict__ bias,
                                                     float* __restrict__ out)
{
    extern __shared__ char smg[];
    uint32_t sb = scvta(smg);
    const int m0 = blockIdx.y * 128;
    const int n0 = blockIdx.x * 256;

    float acc[4][8][4];
    gemm_main(gc_h + (size_t)m0 * 1024, gc_l + (size_t)m0 * 1024,
              gwo_h + (size_t)n0 * 1024, gwo_l + (size_t)n0 * 1024, sb, acc);

    const int t = threadIdx.x;
    const int lane = t & 31, wid = t >> 5;
    const int wm = wid >> 2, wn = wid & 3;
    const int g = lane >> 2, tq = lane & 3;

#pragma unroll
    for (int i = 0; i < 4; i++) {
        int m = m0 + wm * 64 + i * 16 + g;
#pragma unroll
        for (int j = 0; j < 8; j++) {
            int nn = n0 + wn * 64 + j * 8 + 2 * tq;
            float2 bb = *(const float2*)(bias + nn);
            float* p = out + (size_t)m * DOUT + nn;
            *(float2*)p              = make_float2(acc[i][j][0] + bb.x, acc[i][j][1] + bb.y);
            *(float2*)(p + 8 * DOUT) = make_float2(acc[i][j][2] + bb.x, acc[i][j][3] + bb.y);
        }
    }
}

// ===========================================================================
// Attention: 128 queries/CTA, 8 warps. Prefetch cp.async interleaved into
// the S-GEMM MMA stream.
// ===========================================================================
#define APB      144
#define ATILE_B  (64 * APB)
#define ASTAGE_B (4 * ATILE_B)
#define ATTN_SMEM (2 * ASTAGE_B)

__device__ __forceinline__ void aload_tile(const __nv_bfloat16* src, uint32_t dst, int t)
{
#pragma unroll
    for (int i = 0; i < 2; i++) {
        int idx = t + i * 256;
        int row = idx >> 3, c = idx & 7;
        CPA16(dst + row * APB + c * 16, src + (size_t)row * HD_ + c * 8);
    }
}
__device__ __forceinline__ void aload_q(const __nv_bfloat16* src, uint32_t dst, int t)
{
#pragma unroll
    for (int i = 0; i < 4; i++) {
        int idx = t + i * 256;
        int row = idx >> 3, c = idx & 7;
        CPA16(dst + row * APB + c * 16, src + (size_t)row * HD_ + c * 8);
    }
}

// one of 8 per-thread prefetch cps: tile = j>>1 (Khi,Klo,Vhi,Vlo), iter = j&1
__device__ __forceinline__ void docpa(int j, const __nv_bfloat16* kh, const __nv_bfloat16* kl,
                                      const __nv_bfloat16* vh, const __nv_bfloat16* vl,
                                      uint32_t ns, int t)
{
    int tile = j >> 1;
    int idx  = t + (j & 1) * 256;
    int row = idx >> 3, c = idx & 7;
    const __nv_bfloat16* src = (tile == 0) ? kh : (tile == 1) ? kl : (tile == 2) ? vh : vl;
    CPA16(ns + tile * ATILE_B + row * APB + c * 16, src + (size_t)row * HD_ + c * 8);
}

__global__ __launch_bounds__(256, 1) void attn_k()
{
    extern __shared__ char sma[];
    uint32_t sb = scvta(sma);

    const int t    = threadIdx.x;
    const int lane = t & 31;
    const int w    = t >> 5;
    const int g    = lane >> 2;
    const int tq   = lane & 3;

    const int q0 = blockIdx.x * 128;
    const int h  = blockIdx.y;
    const int b  = blockIdx.z;
    const size_t hb = (size_t)(b * NH + h) * S_ * HD_;

    int kc0 = q0 - WIN; if (kc0 < 0) kc0 = 0;
    int kce = q0 + 128 + WIN; if (kce > S_) kce = S_;
    const int nch = (kce - kc0) >> 6;

    aload_tile(gk_h + hb + (size_t)kc0 * HD_, sb,               t);
    aload_tile(gk_l + hb + (size_t)kc0 * HD_, sb + ATILE_B,     t);
    aload_tile(gv_h + hb + (size_t)kc0 * HD_, sb + 2 * ATILE_B, t);
    aload_tile(gv_l + hb + (size_t)kc0 * HD_, sb + 3 * ATILE_B, t);
    CPC();
    aload_q(gq_h + hb + (size_t)q0 * HD_, sb + ASTAGE_B,               t);
    aload_q(gq_l + hb + (size_t)q0 * HD_, sb + ASTAGE_B + 2 * ATILE_B, t);
    CPC();
    CPW(0);
    __syncthreads();

    uint32_t qh[4][4], ql[4][4];
#pragma unroll
    for (int kc = 0; kc < 4; kc++) {
        int r = 16 * w + (lane & 15);
        uint32_t a = sb + ASTAGE_B + r * APB + kc * 32 + (lane >> 4) * 16;
        LDSM4(qh[kc][0], qh[kc][1], qh[kc][2], qh[kc][3], a);
        LDSM4(ql[kc][0], ql[kc][1], ql[kc][2], ql[kc][3], a + 2 * ATILE_B);
    }
    __syncthreads();

    float oacc[8][4];
#pragma unroll
    for (int j = 0; j < 8; j++)
#pragma unroll
        for (int c = 0; c < 4; c++) oacc[j][c] = 0.f;
    float m_[2] = {-INFINITY, -INFINITY};
    float l_[2] = {0.f, 0.f};
    const int row0 = q0 + 16 * w + g;

    for (int c = 0; c < nch; c++) {
        const int kc = kc0 + c * 64;
        if (c) { CPW(0); __syncthreads(); }
        const uint32_t ks = sb + (c & 1) * ASTAGE_B;
        const uint32_t ns = sb + ((c + 1) & 1) * ASTAGE_B;
        const bool pf = (c + 1 < nch);
        const size_t noff = hb + (size_t)(kc + 64) * HD_;

        // ---- S = Q @ K^T (3-pass), prefetch cps interleaved ----
        float sacc[8][4];
#pragma unroll
        for (int j = 0; j < 8; j++)
#pragma unroll
            for (int cc = 0; cc < 4; cc++) sacc[j][cc] = 0.f;

#pragma unroll
        for (int kc2 = 0; kc2 < 4; kc2++) {
#pragma unroll
            for (int jp = 0; jp < 4; jp++) {
                int r = jp * 16 + (lane >> 4) * 8 + (lane & 7);
                uint32_t a = ks + r * APB + kc2 * 32 + ((lane >> 3) & 1) * 16;
                uint32_t bh0[2], bh1[2], bl0[2], bl1[2];
                LDSM4(bh0[0], bh0[1], bh1[0], bh1[1], a);
                LDSM4(bl0[0], bl0[1], bl1[0], bl1[1], a + ATILE_B);
                mma_bf16(sacc[2*jp],   qh[kc2], bh0);
                mma_bf16(sacc[2*jp],   ql[kc2], bh0);
                mma_bf16(sacc[2*jp],   qh[kc2], bl0);
                mma_bf16(sacc[2*jp+1], qh[kc2], bh1);
                mma_bf16(sacc[2*jp+1], ql[kc2], bh1);
                mma_bf16(sacc[2*jp+1], qh[kc2], bl1);
                int gi = kc2 * 4 + jp;
                if (pf && gi < 8)
                    docpa(gi, gk_h + noff, gk_l + noff, gv_h + noff, gv_l + noff, ns, t);
            }
        }
        if (pf) CPC();

        // ---- mask + online softmax ----
#pragma unroll
        for (int half = 0; half < 2; half++) {
            int row = row0 + 8 * half;
            float mx = -INFINITY;
#pragma unroll
            for (int j = 0; j < 8; j++) {
                int col = kc + 8 * j + 2 * tq;
                float v0 = sacc[j][2 * half];
                float v1 = sacc[j][2 * half + 1];
                int d0 = row - col;     d0 = d0 < 0 ? -d0 : d0;
                int d1 = row - col - 1; d1 = d1 < 0 ? -d1 : d1;
                v0 = (d0 <= WIN) ? v0 * SCALE : -INFINITY;
                v1 = (d1 <= WIN) ? v1 * SCALE : -INFINITY;
                sacc[j][2 * half]     = v0;
                sacc[j][2 * half + 1] = v1;
                mx = fmaxf(mx, fmaxf(v0, v1));
            }
            mx = fmaxf(mx, __shfl_xor_sync(0xffffffffu, mx, 1, 4));
            mx = fmaxf(mx, __shfl_xor_sync(0xffffffffu, mx, 2, 4));

            float mn    = fmaxf(m_[half], mx);
            float msafe = (mn == -INFINITY) ? 0.f : mn;
            float alpha = __expf(m_[half] - msafe);
            m_[half] = mn;

            float rs = 0.f;
#pragma unroll
            for (int j = 0; j < 8; j++) {
                float p0 = __expf(sacc[j][2 * half]     - msafe);
                float p1 = __expf(sacc[j][2 * half + 1] - msafe);
                sacc[j][2 * half]     = p0;
                sacc[j][2 * half + 1] = p1;
                rs += p0 + p1;
            }
            rs += __shfl_xor_sync(0xffffffffu, rs, 1, 4);
            rs += __shfl_xor_sync(0xffffffffu, rs, 2, 4);
            l_[half] = l_[half] * alpha + rs;
#pragma unroll
            for (int j = 0; j < 8; j++) {
                oacc[j][2 * half]     *= alpha;
                oacc[j][2 * half + 1] *= alpha;
            }
        }

        // ---- O += P @ V (3-pass, V via ldmatrix.trans) ----
#pragma unroll
        for (int kp = 0; kp < 4; kp++) {
            uint32_t ph[4], pl[4];
            split2(sacc[2*kp][0],   sacc[2*kp][1],   ph[0], pl[0]);
            split2(sacc[2*kp][2],   sacc[2*kp][3],   ph[1], pl[1]);
            split2(sacc[2*kp+1][0], sacc[2*kp+1][1], ph[2], pl[2]);
            split2(sacc[2*kp+1][2], sacc[2*kp+1][3], ph[3], pl[3]);

#pragma unroll
            for (int jp = 0; jp < 4; jp++) {
                int keyrow = kp * 16 + ((lane >> 3) & 1) * 8 + (lane & 7);
                uint32_t a = ks + 2 * ATILE_B + keyrow * APB + (2 * jp + (lane >> 4)) * 16;
                uint32_t vh0[2], vh1[2], vl0[2], vl1[2];
                LDSM4T(vh0[0], vh0[1], vh1[0], vh1[1], a);
                LDSM4T(vl0[0], vl0[1], vl1[0], vl1[1], a + ATILE_B);
                mma_bf16(oacc[2*jp],   ph, vh0);
                mma_bf16(oacc[2*jp],   pl, vh0);
                mma_bf16(oacc[2*jp],   ph, vl0);
                mma_bf16(oacc[2*jp+1], ph, vh1);
                mma_bf16(oacc[2*jp+1], pl, vh1);
                mma_bf16(oacc[2*jp+1], ph, vl1);
            }
        }
    }

    // ---- finalize ----
    float rl0 = 1.f / l_[0];
    float rl1 = 1.f / l_[1];
    size_t c0 = ((size_t)b * S_ + row0) * DOUT + h * HD_;
    size_t c1 = c0 + 8 * DOUT;
#pragma unroll
    for (int j = 0; j < 8; j++) {
        int hd = 8 * j + 2 * tq;
        uint32_t hw, lw;
        split2(oacc[j][0] * rl0, oacc[j][1] * rl0, hw, lw);
        *(uint32_t*)(gc_h + c0 + hd) = hw;
        *(uint32_t*)(gc_l + c0 + hd) = lw;
        split2(oacc[j][2] * rl1, oacc[j][3] * rl1, hw, lw);
        *(uint32_t*)(gc_h + c1 + hd) = hw;
        *(uint32_t*)(gc_l + c1 + hd) = lw;
    }
}

// ===========================================================================
extern "C" void kernel_launch(void* const* d_in, const int* in_sizes, int n_in,
                              void* d_out, int out_size)
{
    const float* x    = (const float*)d_in[0];
    const float* wqkv = (const float*)d_in[1];
    const float* wout = (const float*)d_in[2];
    const float* bout = (const float*)d_in[3];
    float* out = (float*)d_out;

    __nv_bfloat16 *p_xh, *p_xl, *p_qh, *p_ql, *p_oh, *p_ol;
    cudaGetSymbolAddress((void**)&p_xh, gx_h);
    cudaGetSymbolAddress((void**)&p_xl, gx_l);
    cudaGetSymbolAddress((void**)&p_qh, gwq_h);
    cudaGetSymbolAddress((void**)&p_ql, gwq_l);
    cudaGetSymbolAddress((void**)&p_oh, gwo_h);
    cudaGetSymbolAddress((void**)&p_ol, gwo_l);

    cudaFuncSetAttribute(qkv_gemm_k, cudaFuncAttributeMaxDynamicSharedMemorySize, GEMM_SMEM);
    cudaFuncSetAttribute(out_gemm_k, cudaFuncAttributeMaxDynamicSharedMemorySize, GEMM_SMEM);
    cudaFuncSetAttribute(attn_k, cudaFuncAttributeMaxDynamicSharedMemorySize, ATTN_SMEM);

    split_kernel<<<NX / 4 / 256, 256>>>((const float4*)x, (uint2*)p_xh, (uint2*)p_xl, NX / 4);
    split_kernel<<<3 * DOUT * DIN / 4 / 256, 256>>>((const float4*)wqkv, (uint2*)p_qh,
                                                    (uint2*)p_ql, 3 * DOUT * DIN / 4);
    split_kernel<<<DOUT * DOUT / 4 / 256, 256>>>((const float4*)wout, (uint2*)p_oh,
                                                 (uint2*)p_ol, DOUT * DOUT / 4);

    qkv_gemm_k<<<dim3(3 * DOUT / 256, (B_ * S_) / 128), 256, GEMM_SMEM>>>();
    attn_k<<<dim3(S_ / 128, NH, B_), 256, ATTN_SMEM>>>();
    out_gemm_k<<<dim3(DOUT / 256, (B_ * S_) / 128), 256, GEMM_SMEM>>>(bout, out);
}

// round 8
// speedup vs baseline: 3.1290x; 1.0144x over previous
#include <cuda_runtime.h>
#include <cuda_bf16.h>
#include <math.h>
#include <stdint.h>

#define B_    2
#define S_    2048
#define DIN   1024
#define DOUT  1024
#define NH    16
#define HD_   64
#define WIN   256
#define SCALE 0.125f

#define NQKV (B_*NH*S_*HD_)
#define NX   (B_*S_*DIN)

__device__ __align__(16) __nv_bfloat16 gx_h[NX],  gx_l[NX];
__device__ __align__(16) __nv_bfloat16 gwq_h[3*DOUT*DIN], gwq_l[3*DOUT*DIN];
__device__ __align__(16) __nv_bfloat16 gwo_h[DOUT*DOUT],  gwo_l[DOUT*DOUT];
__device__ __align__(16) __nv_bfloat16 gq_h[NQKV], gq_l[NQKV];
__device__ __align__(16) __nv_bfloat16 gk_h[NQKV], gk_l[NQKV];
__device__ __align__(16) __nv_bfloat16 gv_h[NQKV], gv_l[NQKV];
__device__ __align__(16) __nv_bfloat16 gc_h[B_*S_*DOUT], gc_l[B_*S_*DOUT];

// ===========================================================================
__device__ __forceinline__ void split2(float x, float y, uint32_t& hi, uint32_t& lo) {
    __nv_bfloat16 hx = __float2bfloat16(x);
    __nv_bfloat16 hy = __float2bfloat16(y);
    float rx = x - __bfloat162float(hx);
    float ry = y - __bfloat162float(hy);
    __nv_bfloat16 lx = __float2bfloat16(rx);
    __nv_bfloat16 ly = __float2bfloat16(ry);
    __nv_bfloat162 hv; hv.x = hx; hv.y = hy;
    __nv_bfloat162 lv; lv.x = lx; lv.y = ly;
    hi = *(uint32_t*)&hv;
    lo = *(uint32_t*)&lv;
}

__device__ __forceinline__ void mma_bf16(float c[4], const uint32_t a[4], const uint32_t b[2]) {
    asm volatile(
        "mma.sync.aligned.m16n8k16.row.col.f32.bf16.bf16.f32 "
        "{%0,%1,%2,%3}, {%4,%5,%6,%7}, {%8,%9}, {%0,%1,%2,%3};"
        : "+f"(c[0]), "+f"(c[1]), "+f"(c[2]), "+f"(c[3])
        : "r"(a[0]), "r"(a[1]), "r"(a[2]), "r"(a[3]), "r"(b[0]), "r"(b[1]));
}

#define CPA16(dst, src) asm volatile("cp.async.cg.shared.global [%0], [%1], 16;" :: "r"(dst), "l"(src))
#define CPC()  asm volatile("cp.async.commit_group;" ::: "memory")
#define CPW(n) asm volatile("cp.async.wait_group %0;" :: "n"(n) : "memory")

#define LDSM4(d0,d1,d2,d3,a) \
    asm volatile("ldmatrix.sync.aligned.m8n8.x4.shared.b16 {%0,%1,%2,%3}, [%4];" \
                 : "=r"(d0),"=r"(d1),"=r"(d2),"=r"(d3) : "r"(a))
#define LDSM4T(d0,d1,d2,d3,a) \
    asm volatile("ldmatrix.sync.aligned.m8n8.x4.trans.shared.b16 {%0,%1,%2,%3}, [%4];" \
                 : "=r"(d0),"=r"(d1),"=r"(d2),"=r"(d3) : "r"(a))

__device__ __forceinline__ uint32_t scvta(const void* p) {
    return (uint32_t)__cvta_generic_to_shared(p);
}

// ===========================================================================
__global__ void split_kernel(const float4* __restrict__ src, uint2* __restrict__ hi,
                             uint2* __restrict__ lo, int n4)
{
    int i = blockIdx.x * 256 + threadIdx.x;
    if (i < n4) {
        float4 v = src[i];
        uint32_t h0, l0, h1, l1;
        split2(v.x, v.y, h0, l0);
        split2(v.z, v.w, h1, l1);
        hi[i] = make_uint2(h0, h1);
        lo[i] = make_uint2(l0, l1);
    }
}

// ===========================================================================
// GEMM: C[128x256] per CTA, 8 warps (2M x 4N), warp tile 64x64, BK=64,
// 2-stage cp.async, bf16 3-pass, cp/LDSM interleaved among MMA groups.
// ===========================================================================
#define PRB       144                    // 128B payload + 16 pad
#define GA_B      (128 * PRB)            // 18432
#define GB_B      (256 * PRB)            // 36864
#define GSTAGE_B  (2 * GA_B + 2 * GB_B)  // 110592
#define GOFF_AL   GA_B
#define GOFF_BH   (2 * GA_B)
#define GOFF_BL   (GOFF_BH + GB_B)
#define GEMM_SMEM (2 * GSTAGE_B)         // 221184

__device__ __forceinline__ void gstage(const __nv_bfloat16* Ah, const __nv_bfloat16* Al,
                                       const __nv_bfloat16* Bh, const __nv_bfloat16* Bl,
                                       int k0, uint32_t sb, int t)
{
#pragma unroll
    for (int it = 0; it < 4; it++) {         // A hi+lo: 128 rows x 8 cps
        int idx = t + it * 256;
        int row = idx >> 3, c = idx & 7;
        uint32_t d = sb + row * PRB + c * 16;
        CPA16(d,           Ah + (size_t)row * 1024 + k0 + c * 8);
        CPA16(d + GOFF_AL, Al + (size_t)row * 1024 + k0 + c * 8);
    }
#pragma unroll
    for (int it = 0; it < 8; it++) {         // B hi+lo: 256 rows x 8 cps
        int idx = t + it * 256;
        int row = idx >> 3, c = idx & 7;
        uint32_t d = sb + GOFF_BH + row * PRB + c * 16;
        CPA16(d,        Bh + (size_t)row * 1024 + k0 + c * 8);
        CPA16(d + GB_B, Bl + (size_t)row * 1024 + k0 + c * 8);
    }
}

// one of 24 per-thread cp.async ops for a stage
__device__ __forceinline__ void docp(int j,
                                     const __nv_bfloat16* Ah, const __nv_bfloat16* Al,
                                     const __nv_bfloat16* Bh, const __nv_bfloat16* Bl,
                                     int k0, uint32_t sb, int t)
{
    if (j < 8) {
        int it = j & 3;
        int idx = t + it * 256;
        int row = idx >> 3, c = idx & 7;
        uint32_t d = sb + row * PRB + c * 16;
        if (j < 4) CPA16(d,           Ah + (size_t)row * 1024 + k0 + c * 8);
        else       CPA16(d + GOFF_AL, Al + (size_t)row * 1024 + k0 + c * 8);
    } else {
        int jj = j - 8;
        int it = jj & 7;
        int idx = t + it * 256;
        int row = idx >> 3, c = idx & 7;
        uint32_t d = sb + GOFF_BH + row * PRB + c * 16;
        if (jj < 8) CPA16(d,        Bh + (size_t)row * 1024 + k0 + c * 8);
        else        CPA16(d + GB_B, Bl + (size_t)row * 1024 + k0 + c * 8);
    }
}

__device__ __forceinline__ void mma_g8(float (*accr)[4], const uint32_t a[4],
                                       const uint32_t (*b)[2])
{
#pragma unroll
    for (int j = 0; j < 8; j++) mma_bf16(accr[j], a, b[j]);
}

__device__ __forceinline__ void gemm_main(const __nv_bfloat16* Ah, const __nv_bfloat16* Al,
                                          const __nv_bfloat16* Bh, const __nv_bfloat16* Bl,
                                          uint32_t sb, float acc[4][8][4])
{
    const int t = threadIdx.x;
    const int lane = t & 31, wid = t >> 5;
    const int wm = wid >> 2, wn = wid & 3;

#pragma unroll
    for (int i = 0; i < 4; i++)
#pragma unroll
        for (int j = 0; j < 8; j++)
#pragma unroll
            for (int c = 0; c < 4; c++) acc[i][j][c] = 0.f;

    gstage(Ah, Al, Bh, Bl, 0, sb, t);
    CPC();

    for (int ks = 0; ks < 16; ks++) {
        CPW(0);
        __syncthreads();
        const uint32_t cs = sb + (ks & 1) * GSTAGE_B;
        const uint32_t ps = sb + ((ks + 1) & 1) * GSTAGE_B;
        const int k0n = (ks + 1) * 64;
        const bool pf = (ks < 15);

#pragma unroll
        for (int kc = 0; kc < 4; kc++) {
            uint32_t ah[4][4], al[4][4], bh[8][2], bl[8][2];
#pragma unroll
            for (int jp = 0; jp < 4; jp++) {
                int r = wn * 64 + jp * 16 + (lane >> 4) * 8 + (lane & 7);
                uint32_t a = cs + GOFF_BH + r * PRB + kc * 32 + ((lane >> 3) & 1) * 16;
                LDSM4(bh[2*jp][0], bh[2*jp][1], bh[2*jp+1][0], bh[2*jp+1][1], a);
            }
#pragma unroll
            for (int i = 0; i < 4; i++) {
                int r = wm * 64 + i * 16 + (lane & 15);
                LDSM4(ah[i][0], ah[i][1], ah[i][2], ah[i][3],
                      cs + r * PRB + kc * 32 + (lane >> 4) * 16);
            }
#pragma unroll
            for (int i = 0; i < 4; i++) {
                mma_g8(acc[i], ah[i], bh);
                int r = wm * 64 + i * 16 + (lane & 15);
                LDSM4(al[i][0], al[i][1], al[i][2], al[i][3],
                      cs + GOFF_AL + r * PRB + kc * 32 + (lane >> 4) * 16);
                int gi = kc * 12 + i;
                if (pf && gi < 24) docp(gi, Ah, Al, Bh, Bl, k0n, ps, t);
            }
#pragma unroll
            for (int i = 0; i < 4; i++) {
                mma_g8(acc[i], al[i], bh);
                int r = wn * 64 + i * 16 + (lane >> 4) * 8 + (lane & 7);
                uint32_t a = cs + GOFF_BL + r * PRB + kc * 32 + ((lane >> 3) & 1) * 16;
                LDSM4(bl[2*i][0], bl[2*i][1], bl[2*i+1][0], bl[2*i+1][1], a);
                int gi = kc * 12 + 4 + i;
                if (pf && gi < 24) docp(gi, Ah, Al, Bh, Bl, k0n, ps, t);
            }
#pragma unroll
            for (int i = 0; i < 4; i++) {
                mma_g8(acc[i], ah[i], bl);
                int gi = kc * 12 + 8 + i;
                if (pf && gi < 24) docp(gi, Ah, Al, Bh, Bl, k0n, ps, t);
            }
        }
        CPC();
    }
}

__global__ __launch_bounds__(256, 1) void qkv_gemm_k()
{
    extern __shared__ char smg[];
    uint32_t sb = scvta(smg);
    const int m0 = blockIdx.y * 128;
    const int n0 = blockIdx.x * 256;

    float acc[4][8][4];
    gemm_main(gx_h + (size_t)m0 * 1024, gx_l + (size_t)m0 * 1024,
              gwq_h + (size_t)n0 * 1024, gwq_l + (size_t)n0 * 1024, sb, acc);

    const int t = threadIdx.x;
    const int lane = t & 31, wid = t >> 5;
    const int wm = wid >> 2, wn = wid & 3;
    const int g = lane >> 2, tq = lane & 3;

    const int which = n0 >> 10;
    __nv_bfloat16* dh = (which == 0) ? gq_h : (which == 1) ? gk_h : gv_h;
    __nv_bfloat16* dl = (which == 0) ? gq_l : (which == 1) ? gk_l : gv_l;
    const int h = ((n0 + wn * 64) >> 6) & (NH - 1);

#pragma unroll
    for (int i = 0; i < 4; i++) {
        int m = m0 + wm * 64 + i * 16 + g;
        int b = m >> 11, s = m & (S_ - 1);
#pragma unroll
        for (int j = 0; j < 8; j++) {
            int hd = j * 8 + 2 * tq;
            size_t idx = (((size_t)(b * NH + h) * S_ + s) * HD_ + hd);
            uint32_t hw, lw;
            split2(acc[i][j][0], acc[i][j][1], hw, lw);
            *(uint32_t*)(dh + idx) = hw;
            *(uint32_t*)(dl + idx) = lw;
            split2(acc[i][j][2], acc[i][j][3], hw, lw);
            *(uint32_t*)(dh + idx + 8 * HD_) = hw;
            *(uint32_t*)(dl + idx + 8 * HD_) = lw;
        }
    }
}

__global__ __launch_bounds__(256, 1) void out_gemm_k(const float* __restrict__ bias,
                                                     float* __restrict__ out)
{
    extern __shared__ char smg[];
    uint32_t sb = scvta(smg);
    const int m0 = blockIdx.y * 128;
    const int n0 = blockIdx.x * 256;

    float acc[4][8][4];
    gemm_main(gc_h + (size_t)m0 * 1024, gc_l + (size_t)m0 * 1024,
              gwo_h + (size_t)n0 * 1024, gwo_l + (size_t)n0 * 1024, sb, acc);

    const int t = threadIdx.x;
    const int lane = t & 31, wid = t >> 5;
    const int wm = wid >> 2, wn = wid & 3;
    const int g = lane >> 2, tq = lane & 3;

#pragma unroll
    for (int i = 0; i < 4; i++) {
        int m = m0 + wm * 64 + i * 16 + g;
#pragma unroll
        for (int j = 0; j < 8; j++) {
            int nn = n0 + wn * 64 + j * 8 + 2 * tq;
            float2 bb = *(const float2*)(bias + nn);
            float* p = out + (size_t)m * DOUT + nn;
            *(float2*)p              = make_float2(acc[i][j][0] + bb.x, acc[i][j][1] + bb.y);
            *(float2*)(p + 8 * DOUT) = make_float2(acc[i][j][2] + bb.x, acc[i][j][3] + bb.y);
        }
    }
}

// ===========================================================================
// Attention: 256 queries/CTA, 8 warps; warp w owns rows 32w..32w+31 as two
// 16-row blocks. Per-block chunk skipping (fully-masked chunks). K/V chunk 64
// double-buffered; prefetch interleaved into block0's S-MMA stream.
// ===========================================================================
#define ATQ      256
#define APB      144
#define ATILE_B  (64 * APB)            // 9216
#define ASTAGE_B (4 * ATILE_B)         // 36864
#define AQ_B     (256 * APB)           // 36864 (Q hi; Q lo same)
#define ATTN_SMEM (2 * ASTAGE_B)       // 73728 (Q staged in same space first)

__device__ __forceinline__ void aload_tile(const __nv_bfloat16* src, uint32_t dst, int t)
{
#pragma unroll
    for (int it = 0; it < 2; it++) {
        int idx = t + it * 256;
        int row = idx >> 3, c = idx & 7;
        CPA16(dst + row * APB + c * 16, src + (size_t)row * HD_ + c * 8);
    }
}
__device__ __forceinline__ void aload_q(const __nv_bfloat16* src, uint32_t dst, int t)
{
#pragma unroll
    for (int it = 0; it < 8; it++) {
        int idx = t + it * 256;
        int row = idx >> 3, c = idx & 7;
        CPA16(dst + row * APB + c * 16, src + (size_t)row * HD_ + c * 8);
    }
}

__device__ __forceinline__ void docpa(int j, const __nv_bfloat16* kh, const __nv_bfloat16* kl,
                                      const __nv_bfloat16* vh, const __nv_bfloat16* vl,
                                      uint32_t ns, int t)
{
    int tile = j >> 1;
    int idx  = t + (j & 1) * 256;
    int row = idx >> 3, c = idx & 7;
    const __nv_bfloat16* src = (tile == 0) ? kh : (tile == 1) ? kl : (tile == 2) ? vh : vl;
    CPA16(ns + tile * ATILE_B + row * APB + c * 16, src + (size_t)row * HD_ + c * 8);
}

// process one 16-row block against one 64-key chunk
__device__ __forceinline__ void attn_block(
    uint32_t ks, int kc, int row0,
    const uint32_t (*qh)[4], const uint32_t (*ql)[4],
    float* m_, float* l_, float (*oacc)[4],
    bool dopf,
    const __nv_bfloat16* kh, const __nv_bfloat16* kl,
    const __nv_bfloat16* vh, const __nv_bfloat16* vl,
    uint32_t ns, int t, int lane, int g, int tq)
{
    float sacc[8][4];
#pragma unroll
    for (int j = 0; j < 8; j++)
#pragma unroll
        for (int cc = 0; cc < 4; cc++) sacc[j][cc] = 0.f;

#pragma unroll
    for (int kc2 = 0; kc2 < 4; kc2++) {
#pragma unroll
        for (int jp = 0; jp < 4; jp++) {
            int r = jp * 16 + (lane >> 4) * 8 + (lane & 7);
            uint32_t a = ks + r * APB + kc2 * 32 + ((lane >> 3) & 1) * 16;
            uint32_t bh0[2], bh1[2], bl0[2], bl1[2];
            LDSM4(bh0[0], bh0[1], bh1[0], bh1[1], a);
            LDSM4(bl0[0], bl0[1], bl1[0], bl1[1], a + ATILE_B);
            mma_bf16(sacc[2*jp],   qh[kc2], bh0);
            mma_bf16(sacc[2*jp],   ql[kc2], bh0);
            mma_bf16(sacc[2*jp],   qh[kc2], bl0);
            mma_bf16(sacc[2*jp+1], qh[kc2], bh1);
            mma_bf16(sacc[2*jp+1], ql[kc2], bh1);
            mma_bf16(sacc[2*jp+1], qh[kc2], bl1);
            int gi = kc2 * 4 + jp;
            if (dopf && gi < 8) docpa(gi, kh, kl, vh, vl, ns, t);
        }
    }

#pragma unroll
    for (int half = 0; half < 2; half++) {
        int row = row0 + 8 * half;
        float mx = -INFINITY;
#pragma unroll
        for (int j = 0; j < 8; j++) {
            int col = kc + 8 * j + 2 * tq;
            float v0 = sacc[j][2 * half];
            float v1 = sacc[j][2 * half + 1];
            int d0 = row - col;     d0 = d0 < 0 ? -d0 : d0;
            int d1 = row - col - 1; d1 = d1 < 0 ? -d1 : d1;
            v0 = (d0 <= WIN) ? v0 * SCALE : -INFINITY;
            v1 = (d1 <= WIN) ? v1 * SCALE : -INFINITY;
            sacc[j][2 * half]     = v0;
            sacc[j][2 * half + 1] = v1;
            mx = fmaxf(mx, fmaxf(v0, v1));
        }
        mx = fmaxf(mx, __shfl_xor_sync(0xffffffffu, mx, 1, 4));
        mx = fmaxf(mx, __shfl_xor_sync(0xffffffffu, mx, 2, 4));

        float mn    = fmaxf(m_[half], mx);
        float msafe = (mn == -INFINITY) ? 0.f : mn;
        float alpha = __expf(m_[half] - msafe);
        m_[half] = mn;

        float rs = 0.f;
#pragma unroll
        for (int j = 0; j < 8; j++) {
            float p0 = __expf(sacc[j][2 * half]     - msafe);
            float p1 = __expf(sacc[j][2 * half + 1] - msafe);
            sacc[j][2 * half]     = p0;
            sacc[j][2 * half + 1] = p1;
            rs += p0 + p1;
        }
        rs += __shfl_xor_sync(0xffffffffu, rs, 1, 4);
        rs += __shfl_xor_sync(0xffffffffu, rs, 2, 4);
        l_[half] = l_[half] * alpha + rs;
#pragma unroll
        for (int j = 0; j < 8; j++) {
            oacc[j][2 * half]     *= alpha;
            oacc[j][2 * half + 1] *= alpha;
        }
    }

#pragma unroll
    for (int kp = 0; kp < 4; kp++) {
        uint32_t ph[4], pl[4];
        split2(sacc[2*kp][0],   sacc[2*kp][1],   ph[0], pl[0]);
        split2(sacc[2*kp][2],   sacc[2*kp][3],   ph[1], pl[1]);
        split2(sacc[2*kp+1][0], sacc[2*kp+1][1], ph[2], pl[2]);
        split2(sacc[2*kp+1][2], sacc[2*kp+1][3], ph[3], pl[3]);

#pragma unroll
        for (int jp = 0; jp < 4; jp++) {
            int keyrow = kp * 16 + ((lane >> 3) & 1) * 8 + (lane & 7);
            uint32_t a = ks + 2 * ATILE_B + keyrow * APB + (2 * jp + (lane >> 4)) * 16;
            uint32_t vh0[2], vh1[2], vl0[2], vl1[2];
            LDSM4T(vh0[0], vh0[1], vh1[0], vh1[1], a);
            LDSM4T(vl0[0], vl0[1], vl1[0], vl1[1], a + ATILE_B);
            mma_bf16(oacc[2*jp],   ph, vh0);
            mma_bf16(oacc[2*jp],   pl, vh0);
            mma_bf16(oacc[2*jp],   ph, vl0);
            mma_bf16(oacc[2*jp+1], ph, vh1);
            mma_bf16(oacc[2*jp+1], pl, vh1);
            mma_bf16(oacc[2*jp+1], ph, vl1);
        }
    }
}

__global__ __launch_bounds__(256, 1) void attn_k()
{
    extern __shared__ char sma[];
    uint32_t sb = scvta(sma);

    const int t    = threadIdx.x;
    const int lane = t & 31;
    const int w    = t >> 5;
    const int g    = lane >> 2;
    const int tq   = lane & 3;

    const int q0 = blockIdx.x * ATQ;
    const int h  = blockIdx.y;
    const int b  = blockIdx.z;
    const size_t hb = (size_t)(b * NH + h) * S_ * HD_;

    int kc0 = q0 - WIN; if (kc0 < 0) kc0 = 0;
    int kce = q0 + ATQ + WIN; if (kce > S_) kce = S_;
    const int nch = (kce - kc0) >> 6;

    // --- Q staged through smem (hi -> stage0 area, lo -> stage1 area) ---
    aload_q(gq_h + hb + (size_t)q0 * HD_, sb,            t);
    aload_q(gq_l + hb + (size_t)q0 * HD_, sb + AQ_B,     t);
    CPC();
    CPW(0);
    __syncthreads();

    uint32_t qh[2][4][4], ql[2][4][4];
#pragma unroll
    for (int blk = 0; blk < 2; blk++) {
        int r = 32 * w + 16 * blk + (lane & 15);
#pragma unroll
        for (int kc = 0; kc < 4; kc++) {
            uint32_t a = sb + r * APB + kc * 32 + (lane >> 4) * 16;
            LDSM4(qh[blk][kc][0], qh[blk][kc][1], qh[blk][kc][2], qh[blk][kc][3], a);
            LDSM4(ql[blk][kc][0], ql[blk][kc][1], ql[blk][kc][2], ql[blk][kc][3], a + AQ_B);
        }
    }
    __syncthreads();

    // chunk0 K/V -> stage0
    {
        size_t off = hb + (size_t)kc0 * HD_;
        aload_tile(gk_h + off, sb,               t);
        aload_tile(gk_l + off, sb + ATILE_B,     t);
        aload_tile(gv_h + off, sb + 2 * ATILE_B, t);
        aload_tile(gv_l + off, sb + 3 * ATILE_B, t);
    }
    CPC();

    float oacc[2][8][4];
#pragma unroll
    for (int blk = 0; blk < 2; blk++)
#pragma unroll
        for (int j = 0; j < 8; j++)
#pragma unroll
            for (int c = 0; c < 4; c++) oacc[blk][j][c] = 0.f;
    float m_[2][2] = {{-INFINITY, -INFINITY}, {-INFINITY, -INFINITY}};
    float l_[2][2] = {{0.f, 0.f}, {0.f, 0.f}};

    const int qlo0 = q0 + 32 * w;
    const int qlo1 = qlo0 + 16;

    for (int c = 0; c < nch; c++) {
        const int kc = kc0 + c * 64;
        CPW(0);
        __syncthreads();
        const uint32_t ks = sb + (c & 1) * ASTAGE_B;
        const uint32_t ns = sb + ((c + 1) & 1) * ASTAGE_B;
        const bool pf = (c + 1 < nch);
        const size_t noff = hb + (size_t)(kc + 64) * HD_;
        const __nv_bfloat16 *kh = gk_h + noff, *kl = gk_l + noff;
        const __nv_bfloat16 *vh = gv_h + noff, *vl = gv_l + noff;

        bool a0 = (kc + 64 > qlo0 - WIN) && (kc <= qlo0 + 15 + WIN);
        bool a1 = (kc + 64 > qlo1 - WIN) && (kc <= qlo1 + 15 + WIN);

        if (pf && !a0) {
#pragma unroll
            for (int j = 0; j < 8; j++) docpa(j, kh, kl, vh, vl, ns, t);
        }
        if (a0)
            attn_block(ks, kc, qlo0 + g, qh[0], ql[0], m_[0], l_[0], oacc[0],
                       pf, kh, kl, vh, vl, ns, t, lane, g, tq);
        if (a1)
            attn_block(ks, kc, qlo1 + g, qh[1], ql[1], m_[1], l_[1], oacc[1],
                       false, kh, kl, vh, vl, ns, t, lane, g, tq);
        CPC();
    }

    // ---- finalize both blocks ----
#pragma unroll
    for (int blk = 0; blk < 2; blk++) {
        int row0 = q0 + 32 * w + 16 * blk + g;
        float rl0 = 1.f / l_[blk][0];
        float rl1 = 1.f / l_[blk][1];
        size_t c0 = ((size_t)b * S_ + row0) * DOUT + h * HD_;
        size_t c1 = c0 + 8 * DOUT;
#pragma unroll
        for (int j = 0; j < 8; j++) {
            int hd = 8 * j + 2 * tq;
            uint32_t hw, lw;
            split2(oacc[blk][j][0] * rl0, oacc[blk][j][1] * rl0, hw, lw);
            *(uint32_t*)(gc_h + c0 + hd) = hw;
            *(uint32_t*)(gc_l + c0 + hd) = lw;
            split2(oacc[blk][j][2] * rl1, oacc[blk][j][3] * rl1, hw, lw);
            *(uint32_t*)(gc_h + c1 + hd) = hw;
            *(uint32_t*)(gc_l + c1 + hd) = lw;
        }
    }
}

// ===========================================================================
extern "C" void kernel_launch(void* const* d_in, const int* in_sizes, int n_in,
                              void* d_out, int out_size)
{
    const float* x    = (const float*)d_in[0];
    const float* wqkv = (const float*)d_in[1];
    const float* wout = (const float*)d_in[2];
    const float* bout = (const float*)d_in[3];
    float* out = (float*)d_out;

    __nv_bfloat16 *p_xh, *p_xl, *p_qh, *p_ql, *p_oh, *p_ol;
    cudaGetSymbolAddress((void**)&p_xh, gx_h);
    cudaGetSymbolAddress((void**)&p_xl, gx_l);
    cudaGetSymbolAddress((void**)&p_qh, gwq_h);
    cudaGetSymbolAddress((void**)&p_ql, gwq_l);
    cudaGetSymbolAddress((void**)&p_oh, gwo_h);
    cudaGetSymbolAddress((void**)&p_ol, gwo_l);

    cudaFuncSetAttribute(qkv_gemm_k, cudaFuncAttributeMaxDynamicSharedMemorySize, GEMM_SMEM);
    cudaFuncSetAttribute(out_gemm_k, cudaFuncAttributeMaxDynamicSharedMemorySize, GEMM_SMEM);
    cudaFuncSetAttribute(attn_k, cudaFuncAttributeMaxDynamicSharedMemorySize, ATTN_SMEM);

    split_kernel<<<NX / 4 / 256, 256>>>((const float4*)x, (uint2*)p_xh, (uint2*)p_xl, NX / 4);
    split_kernel<<<3 * DOUT * DIN / 4 / 256, 256>>>((const float4*)wqkv, (uint2*)p_qh,
                                                    (uint2*)p_ql, 3 * DOUT * DIN / 4);
    split_kernel<<<DOUT * DOUT / 4 / 256, 256>>>((const float4*)wout, (uint2*)p_oh,
                                                 (uint2*)p_ol, DOUT * DOUT / 4);

    qkv_gemm_k<<<dim3(3 * DOUT / 256, (B_ * S_) / 128), 256, GEMM_SMEM>>>();
    attn_k<<<dim3(S_ / ATQ, NH, B_), 256, ATTN_SMEM>>>();
    out_gemm_k<<<dim3(DOUT / 256, (B_ * S_) / 128), 256, GEMM_SMEM>>>(bout, out);
}

// round 9
// speedup vs baseline: 3.2079x; 1.0252x over previous
#include <cuda_runtime.h>
#include <cuda_bf16.h>
#include <math.h>
#include <stdint.h>

#define B_    2
#define S_    2048
#define DIN   1024
#define DOUT  1024
#define NH    16
#define HD_   64
#define WIN   256
#define SCALE 0.125f

#define NQKV (B_*NH*S_*HD_)
#define NX   (B_*S_*DIN)

__device__ __align__(16) __nv_bfloat16 gx_h[NX],  gx_l[NX];
__device__ __align__(16) __nv_bfloat16 gwq_h[3*DOUT*DIN], gwq_l[3*DOUT*DIN];
__device__ __align__(16) __nv_bfloat16 gwo_h[DOUT*DOUT],  gwo_l[DOUT*DOUT];
__device__ __align__(16) __nv_bfloat16 gq_h[NQKV], gq_l[NQKV];
__device__ __align__(16) __nv_bfloat16 gk_h[NQKV], gk_l[NQKV];
__device__ __align__(16) __nv_bfloat16 gv_h[NQKV], gv_l[NQKV];
__device__ __align__(16) __nv_bfloat16 gc_h[B_*S_*DOUT], gc_l[B_*S_*DOUT];

// ===========================================================================
__device__ __forceinline__ void split2(float x, float y, uint32_t& hi, uint32_t& lo) {
    __nv_bfloat16 hx = __float2bfloat16(x);
    __nv_bfloat16 hy = __float2bfloat16(y);
    float rx = x - __bfloat162float(hx);
    float ry = y - __bfloat162float(hy);
    __nv_bfloat16 lx = __float2bfloat16(rx);
    __nv_bfloat16 ly = __float2bfloat16(ry);
    __nv_bfloat162 hv; hv.x = hx; hv.y = hy;
    __nv_bfloat162 lv; lv.x = lx; lv.y = ly;
    hi = *(uint32_t*)&hv;
    lo = *(uint32_t*)&lv;
}

__device__ __forceinline__ void mma_bf16(float c[4], const uint32_t a[4], const uint32_t b[2]) {
    asm volatile(
        "mma.sync.aligned.m16n8k16.row.col.f32.bf16.bf16.f32 "
        "{%0,%1,%2,%3}, {%4,%5,%6,%7}, {%8,%9}, {%0,%1,%2,%3};"
        : "+f"(c[0]), "+f"(c[1]), "+f"(c[2]), "+f"(c[3])
        : "r"(a[0]), "r"(a[1]), "r"(a[2]), "r"(a[3]), "r"(b[0]), "r"(b[1]));
}

#define CPA16(dst, src) asm volatile("cp.async.cg.shared.global [%0], [%1], 16;" :: "r"(dst), "l"(src))
#define CPC()  asm volatile("cp.async.commit_group;" ::: "memory")
#define CPW(n) asm volatile("cp.async.wait_group %0;" :: "n"(n) : "memory")

#define LDSM4(d0,d1,d2,d3,a) \
    asm volatile("ldmatrix.sync.aligned.m8n8.x4.shared.b16 {%0,%1,%2,%3}, [%4];" \
                 : "=r"(d0),"=r"(d1),"=r"(d2),"=r"(d3) : "r"(a))
#define LDSM4T(d0,d1,d2,d3,a) \
    asm volatile("ldmatrix.sync.aligned.m8n8.x4.trans.shared.b16 {%0,%1,%2,%3}, [%4];" \
                 : "=r"(d0),"=r"(d1),"=r"(d2),"=r"(d3) : "r"(a))

__device__ __forceinline__ uint32_t scvta(const void* p) {
    return (uint32_t)__cvta_generic_to_shared(p);
}

// ===========================================================================
__global__ void split_kernel(const float4* __restrict__ src, uint2* __restrict__ hi,
                             uint2* __restrict__ lo, int n4)
{
    int i = blockIdx.x * 256 + threadIdx.x;
    if (i < n4) {
        float4 v = src[i];
        uint32_t h0, l0, h1, l1;
        split2(v.x, v.y, h0, l0);
        split2(v.z, v.w, h1, l1);
        hi[i] = make_uint2(h0, h1);
        lo[i] = make_uint2(l0, l1);
    }
}

// ===========================================================================
// GEMM: C[128x256] per CTA, 8 warps (2M x 4N), warp tile 64x64, BK=64,
// 2-stage cp.async, bf16 3-pass, cp/LDSM interleaved among MMA groups.
// (unchanged from R8)
// ===========================================================================
#define PRB       144
#define GA_B      (128 * PRB)
#define GB_B      (256 * PRB)
#define GSTAGE_B  (2 * GA_B + 2 * GB_B)
#define GOFF_AL   GA_B
#define GOFF_BH   (2 * GA_B)
#define GOFF_BL   (GOFF_BH + GB_B)
#define GEMM_SMEM (2 * GSTAGE_B)

__device__ __forceinline__ void gstage(const __nv_bfloat16* Ah, const __nv_bfloat16* Al,
                                       const __nv_bfloat16* Bh, const __nv_bfloat16* Bl,
                                       int k0, uint32_t sb, int t)
{
#pragma unroll
    for (int it = 0; it < 4; it++) {
        int idx = t + it * 256;
        int row = idx >> 3, c = idx & 7;
        uint32_t d = sb + row * PRB + c * 16;
        CPA16(d,           Ah + (size_t)row * 1024 + k0 + c * 8);
        CPA16(d + GOFF_AL, Al + (size_t)row * 1024 + k0 + c * 8);
    }
#pragma unroll
    for (int it = 0; it < 8; it++) {
        int idx = t + it * 256;
        int row = idx >> 3, c = idx & 7;
        uint32_t d = sb + GOFF_BH + row * PRB + c * 16;
        CPA16(d,        Bh + (size_t)row * 1024 + k0 + c * 8);
        CPA16(d + GB_B, Bl + (size_t)row * 1024 + k0 + c * 8);
    }
}

__device__ __forceinline__ void docp(int j,
                                     const __nv_bfloat16* Ah, const __nv_bfloat16* Al,
                                     const __nv_bfloat16* Bh, const __nv_bfloat16* Bl,
                                     int k0, uint32_t sb, int t)
{
    if (j < 8) {
        int it = j & 3;
        int idx = t + it * 256;
        int row = idx >> 3, c = idx & 7;
        uint32_t d = sb + row * PRB + c * 16;
        if (j < 4) CPA16(d,           Ah + (size_t)row * 1024 + k0 + c * 8);
        else       CPA16(d + GOFF_AL, Al + (size_t)row * 1024 + k0 + c * 8);
    } else {
        int jj = j - 8;
        int it = jj & 7;
        int idx = t + it * 256;
        int row = idx >> 3, c = idx & 7;
        uint32_t d = sb + GOFF_BH + row * PRB + c * 16;
        if (jj < 8) CPA16(d,        Bh + (size_t)row * 1024 + k0 + c * 8);
        else        CPA16(d + GB_B, Bl + (size_t)row * 1024 + k0 + c * 8);
    }
}

__device__ __forceinline__ void mma_g8(float (*accr)[4], const uint32_t a[4],
                                       const uint32_t (*b)[2])
{
#pragma unroll
    for (int j = 0; j < 8; j++) mma_bf16(accr[j], a, b[j]);
}

__device__ __forceinline__ void gemm_main(const __nv_bfloat16* Ah, const __nv_bfloat16* Al,
                                          const __nv_bfloat16* Bh, const __nv_bfloat16* Bl,
                                          uint32_t sb, float acc[4][8][4])
{
    const int t = threadIdx.x;
    const int lane = t & 31, wid = t >> 5;
    const int wm = wid >> 2, wn = wid & 3;

#pragma unroll
    for (int i = 0; i < 4; i++)
#pragma unroll
        for (int j = 0; j < 8; j++)
#pragma unroll
            for (int c = 0; c < 4; c++) acc[i][j][c] = 0.f;

    gstage(Ah, Al, Bh, Bl, 0, sb, t);
    CPC();

    for (int ks = 0; ks < 16; ks++) {
        CPW(0);
        __syncthreads();
        const uint32_t cs = sb + (ks & 1) * GSTAGE_B;
        const uint32_t ps = sb + ((ks + 1) & 1) * GSTAGE_B;
        const int k0n = (ks + 1) * 64;
        const bool pf = (ks < 15);

#pragma unroll
        for (int kc = 0; kc < 4; kc++) {
            uint32_t ah[4][4], al[4][4], bh[8][2], bl[8][2];
#pragma unroll
            for (int jp = 0; jp < 4; jp++) {
                int r = wn * 64 + jp * 16 + (lane >> 4) * 8 + (lane & 7);
                uint32_t a = cs + GOFF_BH + r * PRB + kc * 32 + ((lane >> 3) & 1) * 16;
                LDSM4(bh[2*jp][0], bh[2*jp][1], bh[2*jp+1][0], bh[2*jp+1][1], a);
            }
#pragma unroll
            for (int i = 0; i < 4; i++) {
                int r = wm * 64 + i * 16 + (lane & 15);
                LDSM4(ah[i][0], ah[i][1], ah[i][2], ah[i][3],
                      cs + r * PRB + kc * 32 + (lane >> 4) * 16);
            }
#pragma unroll
            for (int i = 0; i < 4; i++) {
                mma_g8(acc[i], ah[i], bh);
                int r = wm * 64 + i * 16 + (lane & 15);
                LDSM4(al[i][0], al[i][1], al[i][2], al[i][3],
                      cs + GOFF_AL + r * PRB + kc * 32 + (lane >> 4) * 16);
                int gi = kc * 12 + i;
                if (pf && gi < 24) docp(gi, Ah, Al, Bh, Bl, k0n, ps, t);
            }
#pragma unroll
            for (int i = 0; i < 4; i++) {
                mma_g8(acc[i], al[i], bh);
                int r = wn * 64 + i * 16 + (lane >> 4) * 8 + (lane & 7);
                uint32_t a = cs + GOFF_BL + r * PRB + kc * 32 + ((lane >> 3) & 1) * 16;
                LDSM4(bl[2*i][0], bl[2*i][1], bl[2*i+1][0], bl[2*i+1][1], a);
                int gi = kc * 12 + 4 + i;
                if (pf && gi < 24) docp(gi, Ah, Al, Bh, Bl, k0n, ps, t);
            }
#pragma unroll
            for (int i = 0; i < 4; i++) {
                mma_g8(acc[i], ah[i], bl);
                int gi = kc * 12 + 8 + i;
                if (pf && gi < 24) docp(gi, Ah, Al, Bh, Bl, k0n, ps, t);
            }
        }
        CPC();
    }
}

__global__ __launch_bounds__(256, 1) void qkv_gemm_k()
{
    extern __shared__ char smg[];
    uint32_t sb = scvta(smg);
    const int m0 = blockIdx.y * 128;
    const int n0 = blockIdx.x * 256;

    float acc[4][8][4];
    gemm_main(gx_h + (size_t)m0 * 1024, gx_l + (size_t)m0 * 1024,
              gwq_h + (size_t)n0 * 1024, gwq_l + (size_t)n0 * 1024, sb, acc);

    const int t = threadIdx.x;
    const int lane = t & 31, wid = t >> 5;
    const int wm = wid >> 2, wn = wid & 3;
    const int g = lane >> 2, tq = lane & 3;

    const int which = n0 >> 10;
    __nv_bfloat16* dh = (which == 0) ? gq_h : (which == 1) ? gk_h : gv_h;
    __nv_bfloat16* dl = (which == 0) ? gq_l : (which == 1) ? gk_l : gv_l;
    const int h = ((n0 + wn * 64) >> 6) & (NH - 1);

#pragma unroll
    for (int i = 0; i < 4; i++) {
        int m = m0 + wm * 64 + i * 16 + g;
        int b = m >> 11, s = m & (S_ - 1);
#pragma unroll
        for (int j = 0; j < 8; j++) {
            int hd = j * 8 + 2 * tq;
            size_t idx = (((size_t)(b * NH + h) * S_ + s) * HD_ + hd);
            uint32_t hw, lw;
            split2(acc[i][j][0], acc[i][j][1], hw, lw);
            *(uint32_t*)(dh + idx) = hw;
            *(uint32_t*)(dl + idx) = lw;
            split2(acc[i][j][2], acc[i][j][3], hw, lw);
            *(uint32_t*)(dh + idx + 8 * HD_) = hw;
            *(uint32_t*)(dl + idx + 8 * HD_) = lw;
        }
    }
}

__global__ __launch_bounds__(256, 1) void out_gemm_k(const float* __restrict__ bias,
                                                     float* __restrict__ out)
{
    extern __shared__ char smg[];
    uint32_t sb = scvta(smg);
    const int m0 = blockIdx.y * 128;
    const int n0 = blockIdx.x * 256;

    float acc[4][8][4];
    gemm_main(gc_h + (size_t)m0 * 1024, gc_l + (size_t)m0 * 1024,
              gwo_h + (size_t)n0 * 1024, gwo_l + (size_t)n0 * 1024, sb, acc);

    const int t = threadIdx.x;
    const int lane = t & 31, wid = t >> 5;
    const int wm = wid >> 2, wn = wid & 3;
    const int g = lane >> 2, tq = lane & 3;

#pragma unroll
    for (int i = 0; i < 4; i++) {
        int m = m0 + wm * 64 + i * 16 + g;
#pragma unroll
        for (int j = 0; j < 8; j++) {
            int nn = n0 + wn * 64 + j * 8 + 2 * tq;
            float2 bb = *(const float2*)(bias + nn);
            float* p = out + (size_t)m * DOUT + nn;
            *(float2*)p              = make_float2(acc[i][j][0] + bb.x, acc[i][j][1] + bb.y);
            *(float2*)(p + 8 * DOUT) = make_float2(acc[i][j][2] + bb.x, acc[i][j][3] + bb.y);
        }
    }
}

// ===========================================================================
// Attention: 128 queries/CTA, 128 threads = 4 warps, 2 CTAs/SM (occ 2).
// Warp w owns rows 32w..32w+31 as two 16-row blocks, per-block chunk skip.
// ===========================================================================
#define ATQ      128
#define ANT      128                   // threads
#define APB      144
#define ATILE_B  (64 * APB)            // 9216
#define ASTAGE_B (4 * ATILE_B)         // 36864
#define AQ_B     (128 * APB)           // 18432
#define ATTN_SMEM (2 * ASTAGE_B)       // 73728

__device__ __forceinline__ void aload_tile(const __nv_bfloat16* src, uint32_t dst, int t)
{
#pragma unroll
    for (int it = 0; it < 4; it++) {
        int idx = t + it * ANT;
        int row = idx >> 3, c = idx & 7;
        CPA16(dst + row * APB + c * 16, src + (size_t)row * HD_ + c * 8);
    }
}
__device__ __forceinline__ void aload_q(const __nv_bfloat16* src, uint32_t dst, int t)
{
#pragma unroll
    for (int it = 0; it < 8; it++) {
        int idx = t + it * ANT;
        int row = idx >> 3, c = idx & 7;
        CPA16(dst + row * APB + c * 16, src + (size_t)row * HD_ + c * 8);
    }
}

// one of 16 per-thread prefetch cps: tile = j>>2 (Khi,Klo,Vhi,Vlo), it = j&3
__device__ __forceinline__ void docpa(int j, const __nv_bfloat16* kh, const __nv_bfloat16* kl,
                                      const __nv_bfloat16* vh, const __nv_bfloat16* vl,
                                      uint32_t ns, int t)
{
    int tile = j >> 2;
    int idx  = t + (j & 3) * ANT;
    int row = idx >> 3, c = idx & 7;
    const __nv_bfloat16* src = (tile == 0) ? kh : (tile == 1) ? kl : (tile == 2) ? vh : vl;
    CPA16(ns + tile * ATILE_B + row * APB + c * 16, src + (size_t)row * HD_ + c * 8);
}

__device__ __forceinline__ void attn_block(
    uint32_t ks, int kc, int row0,
    const uint32_t (*qh)[4], const uint32_t (*ql)[4],
    float* m_, float* l_, float (*oacc)[4],
    bool dopf,
    const __nv_bfloat16* kh, const __nv_bfloat16* kl,
    const __nv_bfloat16* vh, const __nv_bfloat16* vl,
    uint32_t ns, int t, int lane, int g, int tq)
{
    float sacc[8][4];
#pragma unroll
    for (int j = 0; j < 8; j++)
#pragma unroll
        for (int cc = 0; cc < 4; cc++) sacc[j][cc] = 0.f;

#pragma unroll
    for (int kc2 = 0; kc2 < 4; kc2++) {
#pragma unroll
        for (int jp = 0; jp < 4; jp++) {
            int r = jp * 16 + (lane >> 4) * 8 + (lane & 7);
            uint32_t a = ks + r * APB + kc2 * 32 + ((lane >> 3) & 1) * 16;
            uint32_t bh0[2], bh1[2], bl0[2], bl1[2];
            LDSM4(bh0[0], bh0[1], bh1[0], bh1[1], a);
            LDSM4(bl0[0], bl0[1], bl1[0], bl1[1], a + ATILE_B);
            mma_bf16(sacc[2*jp],   qh[kc2], bh0);
            mma_bf16(sacc[2*jp],   ql[kc2], bh0);
            mma_bf16(sacc[2*jp],   qh[kc2], bl0);
            mma_bf16(sacc[2*jp+1], qh[kc2], bh1);
            mma_bf16(sacc[2*jp+1], ql[kc2], bh1);
            mma_bf16(sacc[2*jp+1], qh[kc2], bl1);
            int gi = kc2 * 4 + jp;
            if (dopf) docpa(gi, kh, kl, vh, vl, ns, t);
        }
    }

#pragma unroll
    for (int half = 0; half < 2; half++) {
        int row = row0 + 8 * half;
        float mx = -INFINITY;
#pragma unroll
        for (int j = 0; j < 8; j++) {
            int col = kc + 8 * j + 2 * tq;
            float v0 = sacc[j][2 * half];
            float v1 = sacc[j][2 * half + 1];
            int d0 = row - col;     d0 = d0 < 0 ? -d0 : d0;
            int d1 = row - col - 1; d1 = d1 < 0 ? -d1 : d1;
            v0 = (d0 <= WIN) ? v0 * SCALE : -INFINITY;
            v1 = (d1 <= WIN) ? v1 * SCALE : -INFINITY;
            sacc[j][2 * half]     = v0;
            sacc[j][2 * half + 1] = v1;
            mx = fmaxf(mx, fmaxf(v0, v1));
        }
        mx = fmaxf(mx, __shfl_xor_sync(0xffffffffu, mx, 1, 4));
        mx = fmaxf(mx, __shfl_xor_sync(0xffffffffu, mx, 2, 4));

        float mn    = fmaxf(m_[half], mx);
        float msafe = (mn == -INFINITY) ? 0.f : mn;
        float alpha = __expf(m_[half] - msafe);
        m_[half] = mn;

        float rs = 0.f;
#pragma unroll
        for (int j = 0; j < 8; j++) {
            float p0 = __expf(sacc[j][2 * half]     - msafe);
            float p1 = __expf(sacc[j][2 * half + 1] - msafe);
            sacc[j][2 * half]     = p0;
            sacc[j][2 * half + 1] = p1;
            rs += p0 + p1;
        }
        rs += __shfl_xor_sync(0xffffffffu, rs, 1, 4);
        rs += __shfl_xor_sync(0xffffffffu, rs, 2, 4);
        l_[half] = l_[half] * alpha + rs;
#pragma unroll
        for (int j = 0; j < 8; j++) {
            oacc[j][2 * half]     *= alpha;
            oacc[j][2 * half + 1] *= alpha;
        }
    }

#pragma unroll
    for (int kp = 0; kp < 4; kp++) {
        uint32_t ph[4], pl[4];
        split2(sacc[2*kp][0],   sacc[2*kp][1],   ph[0], pl[0]);
        split2(sacc[2*kp][2],   sacc[2*kp][3],   ph[1], pl[1]);
        split2(sacc[2*kp+1][0], sacc[2*kp+1][1], ph[2], pl[2]);
        split2(sacc[2*kp+1][2], sacc[2*kp+1][3], ph[3], pl[3]);

#pragma unroll
        for (int jp = 0; jp < 4; jp++) {
            int keyrow = kp * 16 + ((lane >> 3) & 1) * 8 + (lane & 7);
            uint32_t a = ks + 2 * ATILE_B + keyrow * APB + (2 * jp + (lane >> 4)) * 16;
            uint32_t vh0[2], vh1[2], vl0[2], vl1[2];
            LDSM4T(vh0[0], vh0[1], vh1[0], vh1[1], a);
            LDSM4T(vl0[0], vl0[1], vl1[0], vl1[1], a + ATILE_B);
            mma_bf16(oacc[2*jp],   ph, vh0);
            mma_bf16(oacc[2*jp],   pl, vh0);
            mma_bf16(oacc[2*jp],   ph, vl0);
            mma_bf16(oacc[2*jp+1], ph, vh1);
            mma_bf16(oacc[2*jp+1], pl, vh1);
            mma_bf16(oacc[2*jp+1], ph, vl1);
        }
    }
}

__global__ __launch_bounds__(ANT, 2) void attn_k()
{
    extern __shared__ char sma[];
    uint32_t sb = scvta(sma);

    const int t    = threadIdx.x;
    const int lane = t & 31;
    const int w    = t >> 5;
    const int g    = lane >> 2;
    const int tq   = lane & 3;

    const int q0 = blockIdx.x * ATQ;
    const int h  = blockIdx.y;
    const int b  = blockIdx.z;
    const size_t hb = (size_t)(b * NH + h) * S_ * HD_;

    int kc0 = q0 - WIN; if (kc0 < 0) kc0 = 0;
    int kce = q0 + ATQ + WIN; if (kce > S_) kce = S_;
    const int nch = (kce - kc0) >> 6;

    // --- Q staged through smem (hi -> sb, lo -> sb+AQ_B) ---
    aload_q(gq_h + hb + (size_t)q0 * HD_, sb,        t);
    aload_q(gq_l + hb + (size_t)q0 * HD_, sb + AQ_B, t);
    CPC();
    CPW(0);
    __syncthreads();

    uint32_t qh[2][4][4], ql[2][4][4];
#pragma unroll
    for (int blk = 0; blk < 2; blk++) {
        int r = 32 * w + 16 * blk + (lane & 15);
#pragma unroll
        for (int kc = 0; kc < 4; kc++) {
            uint32_t a = sb + r * APB + kc * 32 + (lane >> 4) * 16;
            LDSM4(qh[blk][kc][0], qh[blk][kc][1], qh[blk][kc][2], qh[blk][kc][3], a);
            LDSM4(ql[blk][kc][0], ql[blk][kc][1], ql[blk][kc][2], ql[blk][kc][3], a + AQ_B);
        }
    }
    __syncthreads();

    // chunk0 K/V -> stage0
    {
        size_t off = hb + (size_t)kc0 * HD_;
        aload_tile(gk_h + off, sb,               t);
        aload_tile(gk_l + off, sb + ATILE_B,     t);
        aload_tile(gv_h + off, sb + 2 * ATILE_B, t);
        aload_tile(gv_l + off, sb + 3 * ATILE_B, t);
    }
    CPC();

    float oacc[2][8][4];
#pragma unroll
    for (int blk = 0; blk < 2; blk++)
#pragma unroll
        for (int j = 0; j < 8; j++)
#pragma unroll
            for (int c = 0; c < 4; c++) oacc[blk][j][c] = 0.f;
    float m_[2][2] = {{-INFINITY, -INFINITY}, {-INFINITY, -INFINITY}};
    float l_[2][2] = {{0.f, 0.f}, {0.f, 0.f}};

    const int qlo0 = q0 + 32 * w;
    const int qlo1 = qlo0 + 16;

    for (int c = 0; c < nch; c++) {
        const int kc = kc0 + c * 64;
        CPW(0);
        __syncthreads();
        const uint32_t ks = sb + (c & 1) * ASTAGE_B;
        const uint32_t ns = sb + ((c + 1) & 1) * ASTAGE_B;
        const bool pf = (c + 1 < nch);
        const size_t noff = hb + (size_t)(kc + 64) * HD_;
        const __nv_bfloat16 *kh = gk_h + noff, *kl = gk_l + noff;
        const __nv_bfloat16 *vh = gv_h + noff, *vl = gv_l + noff;

        bool a0 = (kc + 64 > qlo0 - WIN) && (kc <= qlo0 + 15 + WIN);
        bool a1 = (kc + 64 > qlo1 - WIN) && (kc <= qlo1 + 15 + WIN);

        if (pf && !a0) {
#pragma unroll
            for (int j = 0; j < 16; j++) docpa(j, kh, kl, vh, vl, ns, t);
        }
        if (a0)
            attn_block(ks, kc, qlo0 + g, qh[0], ql[0], m_[0], l_[0], oacc[0],
                       pf, kh, kl, vh, vl, ns, t, lane, g, tq);
        if (a1)
            attn_block(ks, kc, qlo1 + g, qh[1], ql[1], m_[1], l_[1], oacc[1],
                       false, kh, kl, vh, vl, ns, t, lane, g, tq);
        CPC();
    }

    // ---- finalize both blocks ----
#pragma unroll
    for (int blk = 0; blk < 2; blk++) {
        int row0 = q0 + 32 * w + 16 * blk + g;
        float rl0 = 1.f / l_[blk][0];
        float rl1 = 1.f / l_[blk][1];
        size_t c0 = ((size_t)b * S_ + row0) * DOUT + h * HD_;
        size_t c1 = c0 + 8 * DOUT;
#pragma unroll
        for (int j = 0; j < 8; j++) {
            int hd = 8 * j + 2 * tq;
            uint32_t hw, lw;
            split2(oacc[blk][j][0] * rl0, oacc[blk][j][1] * rl0, hw, lw);
            *(uint32_t*)(gc_h + c0 + hd) = hw;
            *(uint32_t*)(gc_l + c0 + hd) = lw;
            split2(oacc[blk][j][2] * rl1, oacc[blk][j][3] * rl1, hw, lw);
            *(uint32_t*)(gc_h + c1 + hd) = hw;
            *(uint32_t*)(gc_l + c1 + hd) = lw;
        }
    }
}

// ===========================================================================
extern "C" void kernel_launch(void* const* d_in, const int* in_sizes, int n_in,
                              void* d_out, int out_size)
{
    const float* x    = (const float*)d_in[0];
    const float* wqkv = (const float*)d_in[1];
    const float* wout = (const float*)d_in[2];
    const float* bout = (const float*)d_in[3];
    float* out = (float*)d_out;

    __nv_bfloat16 *p_xh, *p_xl, *p_qh, *p_ql, *p_oh, *p_ol;
    cudaGetSymbolAddress((void**)&p_xh, gx_h);
    cudaGetSymbolAddress((void**)&p_xl, gx_l);
    cudaGetSymbolAddress((void**)&p_qh, gwq_h);
    cudaGetSymbolAddress((void**)&p_ql, gwq_l);
    cudaGetSymbolAddress((void**)&p_oh, gwo_h);
    cudaGetSymbolAddress((void**)&p_ol, gwo_l);

    cudaFuncSetAttribute(qkv_gemm_k, cudaFuncAttributeMaxDynamicSharedMemorySize, GEMM_SMEM);
    cudaFuncSetAttribute(out_gemm_k, cudaFuncAttributeMaxDynamicSharedMemorySize, GEMM_SMEM);
    cudaFuncSetAttribute(attn_k, cudaFuncAttributeMaxDynamicSharedMemorySize, ATTN_SMEM);

    split_kernel<<<NX / 4 / 256, 256>>>((const float4*)x, (uint2*)p_xh, (uint2*)p_xl, NX / 4);
    split_kernel<<<3 * DOUT * DIN / 4 / 256, 256>>>((const float4*)wqkv, (uint2*)p_qh,
                                                    (uint2*)p_ql, 3 * DOUT * DIN / 4);
    split_kernel<<<DOUT * DOUT / 4 / 256, 256>>>((const float4*)wout, (uint2*)p_oh,
                                                 (uint2*)p_ol, DOUT * DOUT / 4);

    qkv_gemm_k<<<dim3(3 * DOUT / 256, (B_ * S_) / 128), 256, GEMM_SMEM>>>();
    attn_k<<<dim3(S_ / ATQ, NH, B_), ANT, ATTN_SMEM>>>();
    out_gemm_k<<<dim3(DOUT / 256, (B_ * S_) / 128), 256, GEMM_SMEM>>>(bout, out);
}